// round 15
// baseline (speedup 1.0000x reference)
#include <cuda_runtime.h>
#include <cuda_fp16.h>
#include <stdint.h>

#define HWN 9216
#define CN 256
#define BB 2
#define NOUT 648
#define CH_BIG 36
#define CH_IN 4
#define NT_BIG 3
#define MT_IN 144
#define BT64 150
#define PADW 98
#define PROWS 9856
#define QROWS 19712
#define RS_BIG 768

__device__ __align__(128) __half g_qpad[(size_t)4 * QROWS * 64];
__device__ __align__(128) __half g_qh16[(size_t)BB * HWN * 256];
__device__ __align__(128) __half g_qog[(size_t)BB * 8 * HWN * 32];
__device__ __align__(128) __half g_Ain[(size_t)MT_IN * CH_IN * 8192];
__device__ __align__(128) __half g_Bbig[(size_t)NT_BIG * CH_BIG * 16384];
__device__ __align__(128) __half g_Bin[(size_t)CH_IN * 16384];
__device__ float g_conv2[(size_t)BB * HWN * RS_BIG];
__device__ __align__(128) float g_sWt[BB * 6 * 9 * 128];   // [b][r][tap][cg] pre-transposed
__device__ float g_pool[BB * 6 * 128];
__device__ float g_sim[BB * 24 * HWN];
__device__ __align__(16) float g_bpack[768];

__device__ __forceinline__ uint32_t smem_u32(const void* p) {
    uint32_t a;
    asm("{ .reg .u64 t; cvta.to.shared.u64 t, %1; cvt.u32.u64 %0, t; }" : "=r"(a) : "l"(p));
    return a;
}
#define MBINIT(a, c) asm volatile("mbarrier.init.shared.b64 [%0], %1;" ::"r"(a), "r"(c) : "memory")
#define MBEXPECT(a, b) \
    asm volatile("mbarrier.arrive.expect_tx.shared.b64 _, [%0], %1;" ::"r"(a), "r"(b) : "memory")
__device__ __forceinline__ void mbar_wait(uint32_t mbar, uint32_t parity) {
    asm volatile(
        "{\n\t.reg .pred P;\n\t"
        "LAB_%=:\n\t"
        "mbarrier.try_wait.parity.acquire.cta.shared::cta.b64 P, [%0], %1, 0x989680;\n\t"
        "@!P bra LAB_%=;\n\t}" ::"r"(mbar), "r"(parity) : "memory");
}
__device__ __forceinline__ void bulk_g2s(uint32_t dst, const void* src, uint32_t bytes, uint32_t mbar) {
    asm volatile(
        "cp.async.bulk.shared::cluster.global.mbarrier::complete_tx::bytes [%0], [%1], %2, [%3];"
        ::"r"(dst), "l"(src), "r"(bytes), "r"(mbar) : "memory");
}
__device__ __forceinline__ void ldsm4(uint32_t* r, uint32_t addr) {
    asm volatile("ldmatrix.sync.aligned.m8n8.x4.shared.b16 {%0,%1,%2,%3}, [%4];"
                 : "=r"(r[0]), "=r"(r[1]), "=r"(r[2]), "=r"(r[3]) : "r"(addr));
}
__device__ __forceinline__ void mma_f16(float* c, const uint32_t* a, const uint32_t* b) {
    asm volatile(
        "mma.sync.aligned.m16n8k16.row.col.f32.f16.f16.f32 "
        "{%0,%1,%2,%3}, {%4,%5,%6,%7}, {%8,%9}, {%0,%1,%2,%3};"
        : "+f"(c[0]), "+f"(c[1]), "+f"(c[2]), "+f"(c[3])
        : "r"(a[0]), "r"(a[1]), "r"(a[2]), "r"(a[3]), "r"(b[0]), "r"(b[1]));
}
__device__ __forceinline__ void cvt8(const float* v, __half* hv) {
#pragma unroll
    for (int j = 0; j < 8; j++) hv[j] = __float2half_rn(v[j]);
}

// ---- merged prep ----
__global__ void prep_all(const float* __restrict__ qf, const float* __restrict__ sup,
                         const float* __restrict__ inw, const float* __restrict__ inb,
                         const float* __restrict__ gam, const float* __restrict__ bet,
                         const float* __restrict__ ow1, const float* __restrict__ mw1,
                         const float* __restrict__ ow2, const float* __restrict__ mw2,
                         const float* __restrict__ ow4, const float* __restrict__ mw4,
                         const float* __restrict__ ob1, const float* __restrict__ mb1,
                         const float* __restrict__ ob2, const float* __restrict__ mb2,
                         const float* __restrict__ ob4, const float* __restrict__ mb4) {
    __shared__ float xs[2304];
    __shared__ float Wt[32 * 257];
    __shared__ float stats[18];
    int bx = blockIdx.x;
    int tid = threadIdx.x;
    if (bx == 0) {
        for (int idx = tid; idx < 768; idx += 256) {
            float v = 0.f;
            if (idx < NOUT) {
                int d = idx / 216, r = idx - d * 216;
                const float* bb = (r < 144) ? (d == 0 ? ob1 : d == 1 ? ob2 : ob4)
                                            : (d == 0 ? mb1 : d == 1 ? mb2 : mb4);
                v = bb[(r < 144) ? r : r - 144];
            }
            g_bpack[idx] = v;
        }
        return;
    }
    if (bx < 5) {
        int chunk = bx - 1;
        int c0 = chunk * 64;
        char* dst = (char*)(g_Bin + (size_t)chunk * 16384);
#pragma unroll
        for (int i = 0; i < 8; i++) {
            int unit = i * 256 + tid;
            int r = unit >> 3, u = unit & 7;
            float v[8];
#pragma unroll
            for (int j = 0; j < 8; j++) v[j] = inw[(size_t)r * 256 + c0 + u * 8 + j];
            __align__(16) __half hv[8];
            cvt8(v, hv);
            uint32_t off = r * 128 + u * 16;
            uint32_t sw = off ^ ((off >> 3) & 0x70);
            *(uint4*)(dst + sw) = *(uint4*)hv;
        }
        return;
    }
    if (bx < 113) {
        int t = bx - 5;
        int nt = t % 3, chunk = t / 3;
        int tap = chunk >> 2;
        int c0 = (chunk & 3) * 64;
        char* dst = (char*)(g_Bbig + (size_t)(nt * CH_BIG + chunk) * 16384);
#pragma unroll
        for (int i = 0; i < 8; i++) {
            int unit = i * 256 + tid;
            int r = unit >> 3, u = unit & 7;
            int n = nt * 256 + r;
            float v[8];
#pragma unroll
            for (int j = 0; j < 8; j++) v[j] = 0.f;
            if (n < NOUT) {
                int d = n / 216, rr = n - d * 216;
                const float* w = (rr < 144) ? (d == 0 ? ow1 : d == 1 ? ow2 : ow4)
                                            : (d == 0 ? mw1 : d == 1 ? mw2 : mw4);
                int oc = (rr < 144) ? rr : rr - 144;
#pragma unroll
                for (int j = 0; j < 8; j++)
                    v[j] = w[(size_t)oc * 2304 + (size_t)(c0 + u * 8 + j) * 9 + tap];
            }
            __align__(16) __half hv[8];
            cvt8(v, hv);
            uint32_t off = r * 128 + u * 16;
            uint32_t sw = off ^ ((off >> 3) & 0x70);
            *(uint4*)(dst + sw) = *(uint4*)hv;
        }
        return;
    }
    if (bx < 689) {
        int t = bx - 113;
        int mt = t % MT_IN, chunk = t / MT_IN;
        int c0 = chunk * 64;
        char* dst = (char*)(g_Ain + (size_t)(mt * CH_IN + chunk) * 8192);
#pragma unroll
        for (int i = 0; i < 4; i++) {
            int unit = i * 256 + tid;
            int r = unit & 127, u = unit >> 7;
            int m = mt * 128 + r;
            int b = m / HWN, p = m - b * HWN;
            float v[8];
#pragma unroll
            for (int j = 0; j < 8; j++) v[j] = qf[((size_t)b * CN + c0 + u * 8 + j) * HWN + p];
            __align__(16) __half hv[8];
            cvt8(v, hv);
            uint32_t off = r * 128 + u * 16;
            uint32_t sw = off ^ ((off >> 3) & 0x70);
            *(uint4*)(dst + sw) = *(uint4*)hv;
        }
        return;
    }
    {
        int bid = bx - 689;
        int b = bid / 3, ex = bid - b * 3;
        const float* sp = sup + (size_t)(b * 3 + ex) * 2304;
        for (int i = tid; i < 2304; i += 256) xs[i] = sp[i];
        float acc[9];
        float bia = inb[tid];
#pragma unroll
        for (int pos = 0; pos < 9; pos++) acc[pos] = bia;
        for (int k0 = 0; k0 < 256; k0 += 32) {
            __syncthreads();
            for (int i = tid; i < 256 * 32; i += 256) {
                int c = i >> 5, kk = i & 31;
                Wt[kk * 257 + c] = inw[(size_t)c * 256 + k0 + kk];
            }
            __syncthreads();
#pragma unroll
            for (int kk = 0; kk < 32; kk++) {
                float w = Wt[kk * 257 + tid];
#pragma unroll
                for (int pos = 0; pos < 9; pos++) acc[pos] += w * xs[(k0 + kk) * 9 + pos];
            }
        }
        __syncthreads();
#pragma unroll
        for (int pos = 0; pos < 9; pos++) xs[tid * 9 + pos] = acc[pos];
        __syncthreads();
        if (tid < 9) {
            float s1 = 0.f, s2 = 0.f;
            for (int c = 0; c < 256; c++) { float v = xs[c * 9 + tid]; s1 += v; s2 += v * v; }
            float mu = s1 * (1.f / 256.f);
            stats[tid] = mu;
            stats[9 + tid] = rsqrtf(s2 * (1.f / 256.f) - mu * mu + 1e-5f);
        }
        __syncthreads();
        float mx = -1e30f;
        float g = gam[tid], be = bet[tid];
        int r = ex * 2 + (tid >> 7);
        int cg = tid & 127;
#pragma unroll
        for (int pos = 0; pos < 9; pos++) {
            float v = (acc[pos] - stats[pos]) * stats[9 + pos] * g + be;
            g_sWt[((size_t)(b * 6 + r) * 9 + pos) * 128 + cg] = v;
            mx = fmaxf(mx, v);
        }
        g_pool[(b * 6 + r) * 128 + cg] = mx;
    }
}

// ---- in-projection GEMM (M64, 2-stage, 2 CTA/SM) + fused LN epilogue ----
#define STGI 40960
#define SMEM_IN (1024 + 2 * STGI)
__global__ __launch_bounds__(256, 2) void gemm_in_k(const float* __restrict__ bias,
                                                    const float* __restrict__ gam,
                                                    const float* __restrict__ bet) {
    extern __shared__ char smraw[];
    char* basep = (char*)(((uintptr_t)smraw + 1023) & ~(uintptr_t)1023);
    uint32_t sb = smem_u32(basep);
    int mtg = blockIdx.x;
    int mtH = mtg >> 1, mlo = mtg & 1;
    int tid = threadIdx.x, wid = tid >> 5, lane = tid & 31;
    int wm = (wid & 1) * 32, wn = (wid >> 1) * 64;
    uint32_t FULLB = sb, STG = sb + 1024;
    if (tid == 0)
        for (int s = 0; s < 2; s++) MBINIT(FULLB + s * 8, 1);
    __syncthreads();
    auto issue = [&](int ch, int st) {
        uint32_t S = STG + st * STGI;
        MBEXPECT(FULLB + st * 8, 40960u);
        bulk_g2s(S, g_Ain + (size_t)(mtH * CH_IN + ch) * 8192 + mlo * 4096, 8192u, FULLB + st * 8);
        bulk_g2s(S + 8192, g_Bin + (size_t)ch * 16384, 32768u, FULLB + st * 8);
    };
    if (tid == 0) { issue(0, 0); issue(1, 1); }
    float acc[2][8][4];
#pragma unroll
    for (int a = 0; a < 2; a++)
#pragma unroll
        for (int n = 0; n < 8; n++)
#pragma unroll
            for (int c = 0; c < 4; c++) acc[a][n][c] = 0.f;
    int x7 = lane & 7, kuA = lane >> 4, kuB = (lane >> 3) & 1;
    uint32_t offA[2], offB[4];
#pragma unroll
    for (int mt2 = 0; mt2 < 2; mt2++)
        offA[mt2] = (uint32_t)(wm + mt2 * 16 + ((lane >> 3) & 1) * 8 + x7) * 128u;
#pragma unroll
    for (int ng = 0; ng < 4; ng++)
        offB[ng] = (uint32_t)(wn + ng * 16 + ((lane >> 4) << 3) + x7) * 128u;
    for (int ch = 0; ch < CH_IN; ch++) {
        int st = ch & 1;
        mbar_wait(FULLB + st * 8, (uint32_t)((ch >> 1) & 1));
        uint32_t aB = STG + st * STGI, bB = aB + 8192;
#pragma unroll
        for (int ks = 0; ks < 4; ks++) {
            uint32_t cA = (uint32_t)(((ks * 2 + kuA) ^ x7) << 4);
            uint32_t cB = (uint32_t)(((ks * 2 + kuB) ^ x7) << 4);
            uint32_t Ah[2][4];
#pragma unroll
            for (int mt2 = 0; mt2 < 2; mt2++) ldsm4(Ah[mt2], aB + offA[mt2] + cA);
#pragma unroll
            for (int ng = 0; ng < 4; ng++) {
                uint32_t Bh[4];
                ldsm4(Bh, bB + offB[ng] + cB);
#pragma unroll
                for (int h = 0; h < 2; h++) {
                    int n8 = ng * 2 + h;
                    mma_f16(acc[0][n8], Ah[0], &Bh[h * 2]);
                    mma_f16(acc[1][n8], Ah[1], &Bh[h * 2]);
                }
            }
        }
        __syncthreads();
        if (tid == 0 && ch + 2 < CH_IN) issue(ch + 2, st);
    }
    float* tile = (float*)(basep + 1024);
#pragma unroll
    for (int mt2 = 0; mt2 < 2; mt2++)
#pragma unroll
        for (int half = 0; half < 2; half++) {
            int r = wm + mt2 * 16 + (lane >> 2) + half * 8;
            float* trow = tile + (size_t)r * 264;
#pragma unroll
            for (int n8 = 0; n8 < 8; n8++) {
                int col = wn + n8 * 8 + (lane & 3) * 2;
                float2 v = make_float2(acc[mt2][n8][half * 2 + 0] + bias[col],
                                       acc[mt2][n8][half * 2 + 1] + bias[col + 1]);
                *(float2*)&trow[col] = v;
            }
        }
    __syncthreads();
    float gv[8], bv[8];
#pragma unroll
    for (int j = 0; j < 8; j++) {
        int c = lane * 8 + j;
        gv[j] = __ldg(&gam[c]);
        bv[j] = __ldg(&bet[c]);
    }
    for (int rr = 0; rr < 8; rr++) {
        int row = wid * 8 + rr;
        const float* trow = tile + (size_t)row * 264 + lane * 8;
        float4 a = *(const float4*)trow;
        float4 b4 = *(const float4*)(trow + 4);
        float v[8] = {a.x, a.y, a.z, a.w, b4.x, b4.y, b4.z, b4.w};
        float s1 = 0.f, s2 = 0.f;
#pragma unroll
        for (int j = 0; j < 8; j++) { s1 += v[j]; s2 += v[j] * v[j]; }
#pragma unroll
        for (int o = 16; o > 0; o >>= 1) {
            s1 += __shfl_xor_sync(0xffffffffu, s1, o);
            s2 += __shfl_xor_sync(0xffffffffu, s2, o);
        }
        float mu = s1 * (1.f / 256.f);
        float rv = rsqrtf(s2 * (1.f / 256.f) - mu * mu + 1e-5f);
#pragma unroll
        for (int j = 0; j < 8; j++) v[j] = (v[j] - mu) * rv * gv[j] + bv[j];
        __align__(16) __half hv[8];
        cvt8(v, hv);
        int m = mtg * 64 + row;
        *(uint4*)&g_qh16[(size_t)m * 256 + lane * 8] = *(uint4*)hv;
        int b = m / HWN, p = m - b * HWN;
        {
            int og = lane >> 2, chin = (lane & 3) * 8;
            *(uint4*)&g_qog[(((size_t)(b * 8 + og)) * HWN + p) * 32 + chin] = *(uint4*)hv;
        }
        int y = p / 96, x = p - y * 96;
        size_t r_abs = (size_t)b * PROWS + 128 + (size_t)(y + 1) * PADW + (x + 1);
        int cq = lane >> 3, u = lane & 7;
        uint32_t sw = (uint32_t)(u * 16) ^ (((uint32_t)r_abs & 7) << 4);
        char* hb = (char*)(g_qpad + ((size_t)cq * QROWS + r_abs) * 64);
        *(uint4*)(hb + sw) = *(uint4*)hv;
    }
}

// ---- big conv GEMM ----
#define STGB 40960
#define SMEM_BIG (1024 + 2 * STGB)
__global__ __launch_bounds__(256, 2) void gemm_big_k() {
    extern __shared__ char smraw[];
    char* basep = (char*)(((uintptr_t)smraw + 1023) & ~(uintptr_t)1023);
    uint32_t sb = smem_u32(basep);
    int bx = blockIdx.x;
    int mtg = bx / 3, nt = bx - mtg * 3;
    int b = mtg / BT64, mt_local = mtg - b * BT64;
    size_t arowbase = (size_t)b * PROWS + 128 + (size_t)mt_local * 64;
    int tid = threadIdx.x, wid = tid >> 5, lane = tid & 31;
    int wm = (wid & 1) * 32, wn = (wid >> 1) * 64;
    int ngm = 4;
    if (nt == 2) ngm = (wn == 128) ? 1 : (wn == 192) ? 0 : 4;
    uint32_t FULLB = sb, STG = sb + 1024;
    if (tid == 0)
        for (int s = 0; s < 2; s++) MBINIT(FULLB + s * 8, 1);
    __syncthreads();
    auto issue = [&](int ch, int st) {
        uint32_t S = STG + st * STGB;
        MBEXPECT(FULLB + st * 8, 40960u);
        int tap = ch >> 2, cq = ch & 3;
        int shift = (tap / 3 - 1) * PADW + (tap % 3 - 1);
        size_t row0 = arowbase + shift;
        bulk_g2s(S, g_qpad + ((size_t)cq * QROWS + row0) * 64, 8192u, FULLB + st * 8);
        bulk_g2s(S + 8192, g_Bbig + (size_t)(nt * CH_BIG + ch) * 16384, 32768u, FULLB + st * 8);
    };
    if (tid == 0) { issue(0, 0); issue(1, 1); }
    float acc[2][8][4];
#pragma unroll
    for (int a = 0; a < 2; a++)
#pragma unroll
        for (int n = 0; n < 8; n++)
#pragma unroll
            for (int c = 0; c < 4; c++) acc[a][n][c] = 0.f;
    int x7 = lane & 7, kuA = lane >> 4, kuB = (lane >> 3) & 1;
    uint32_t offA[2], offB[4];
#pragma unroll
    for (int mt2 = 0; mt2 < 2; mt2++)
        offA[mt2] = (uint32_t)(wm + mt2 * 16 + ((lane >> 3) & 1) * 8 + x7) * 128u;
#pragma unroll
    for (int ng = 0; ng < 4; ng++)
        offB[ng] = (uint32_t)(wn + ng * 16 + ((lane >> 4) << 3) + x7) * 128u;
    for (int ch = 0; ch < CH_BIG; ch++) {
        int st = ch & 1;
        mbar_wait(FULLB + st * 8, (uint32_t)((ch >> 1) & 1));
        uint32_t aB = STG + st * STGB, bB = aB + 8192;
        int tap = ch >> 2;
        int shift = (tap / 3 - 1) * PADW + (tap % 3 - 1);
        int xA = (x7 + shift) & 7;
        if (ngm == 4) {
#pragma unroll
            for (int ks = 0; ks < 4; ks++) {
                uint32_t cA = (uint32_t)(((ks * 2 + kuA) ^ xA) << 4);
                uint32_t cB = (uint32_t)(((ks * 2 + kuB) ^ x7) << 4);
                uint32_t Ah[2][4];
#pragma unroll
                for (int mt2 = 0; mt2 < 2; mt2++) ldsm4(Ah[mt2], aB + offA[mt2] + cA);
#pragma unroll
                for (int ng = 0; ng < 4; ng++) {
                    uint32_t Bh[4];
                    ldsm4(Bh, bB + offB[ng] + cB);
#pragma unroll
                    for (int h = 0; h < 2; h++) {
                        int n8 = ng * 2 + h;
                        mma_f16(acc[0][n8], Ah[0], &Bh[h * 2]);
                        mma_f16(acc[1][n8], Ah[1], &Bh[h * 2]);
                    }
                }
            }
        } else if (ngm == 1) {
#pragma unroll
            for (int ks = 0; ks < 4; ks++) {
                uint32_t cA = (uint32_t)(((ks * 2 + kuA) ^ xA) << 4);
                uint32_t cB = (uint32_t)(((ks * 2 + kuB) ^ x7) << 4);
                uint32_t Ah[2][4];
#pragma unroll
                for (int mt2 = 0; mt2 < 2; mt2++) ldsm4(Ah[mt2], aB + offA[mt2] + cA);
                uint32_t Bh[4];
                ldsm4(Bh, bB + offB[0] + cB);
#pragma unroll
                for (int h = 0; h < 2; h++) {
                    mma_f16(acc[0][h], Ah[0], &Bh[h * 2]);
                    mma_f16(acc[1][h], Ah[1], &Bh[h * 2]);
                }
            }
        }
        __syncthreads();
        if (tid == 0 && ch + 2 < CH_BIG) issue(ch + 2, st);
    }
#pragma unroll
    for (int mt2 = 0; mt2 < 2; mt2++)
#pragma unroll
        for (int half = 0; half < 2; half++) {
            int r = wm + mt2 * 16 + (lane >> 2) + half * 8;
            int pp = mt_local * 64 + r;
            int yq = pp / PADW, xq = pp - yq * PADW;
            bool ok = (yq >= 1) && (yq <= 96) && (xq >= 1) && (xq <= 96);
            if (!ok) continue;
            float* drow = g_conv2 + ((size_t)(b * HWN + (yq - 1) * 96 + xq - 1)) * RS_BIG;
#pragma unroll
            for (int n8 = 0; n8 < 8; n8++) {
                int col = nt * 256 + wn + n8 * 8 + (lane & 3) * 2;
                float2 v = make_float2(acc[mt2][n8][half * 2 + 0] + g_bpack[col],
                                       acc[mt2][n8][half * 2 + 1] + g_bpack[col + 1]);
                *(float2*)&drow[col] = v;
            }
        }
}

// ---- deform + sim0: direct-LDG weights, smem = tables only (27.6 KB) ----
#define SMEM_DEF 27648
__global__ void deform_sim0() {
    extern __shared__ char shbuf[];
    int bx = blockIdx.x;
    int tid = threadIdx.x;
    int lane8 = tid & 7, pl = tid >> 3;
    if (bx < 1728) {
        uint2* wtab = (uint2*)shbuf;
        int* btab = (int*)(shbuf + 18432);
        int i0 = bx % 12;
        int rest = bx / 12;
        int j0 = rest % 24;
        int z = rest / 24;
        int b = z / 3, dz = z - b * 3;
        int dil = 1 << dz;
        int px = i0 * 8 + (pl & 7);
        int py = j0 * 4 + (pl >> 3);
        int p = py * 96 + px;
        const float* prow = g_conv2 + ((size_t)(b * HWN) + p) * RS_BIG + dz * 216;
        {
            const float* mrow = prow + 144;
            float vals[9];
            float mx = -1e30f;
#pragma unroll
            for (int t = 0; t < 9; t++) {
                vals[t] = __ldg(&mrow[lane8 * 9 + t]);
                mx = fmaxf(mx, vals[t]);
            }
            mx = fmaxf(mx, __shfl_xor_sync(0xffffffffu, mx, 1));
            mx = fmaxf(mx, __shfl_xor_sync(0xffffffffu, mx, 2));
            mx = fmaxf(mx, __shfl_xor_sync(0xffffffffu, mx, 4));
            float s = 0.f;
#pragma unroll
            for (int t = 0; t < 9; t++) { vals[t] = __expf(vals[t] - mx); s += vals[t]; }
            s += __shfl_xor_sync(0xffffffffu, s, 1);
            s += __shfl_xor_sync(0xffffffffu, s, 2);
            s += __shfl_xor_sync(0xffffffffu, s, 4);
            float inv = 1.f / s;
            int og = lane8;
            int ebase = (pl * 8 + og) * 9;
#pragma unroll
            for (int t = 0; t < 9; t++) {
                float m = vals[t] * inv;
                float dy = __ldg(&prow[og * 18 + t * 2]);
                float dx = __ldg(&prow[og * 18 + t * 2 + 1]);
                float fy = (float)(py + (t / 3) * dil - dil) + dy;
                float fx = (float)(px + (t % 3) * dil - dil) + dx;
                int y0 = (int)floorf(fy), x0 = (int)floorf(fx);
                int by = min(max(y0, 0), 94), bxm = min(max(x0, 0), 94);
                float wy0 = fmaxf(0.f, 1.f - fabsf(fy - (float)by));
                float wy1 = fmaxf(0.f, 1.f - fabsf(fy - (float)(by + 1)));
                float wx0 = fmaxf(0.f, 1.f - fabsf(fx - (float)bxm));
                float wx1 = fmaxf(0.f, 1.f - fabsf(fx - (float)(bxm + 1)));
                __half2 wA = __floats2half2_rn(wy0 * wx0 * m, wy0 * wx1 * m);
                __half2 wB = __floats2half2_rn(wy1 * wx0 * m, wy1 * wx1 * m);
                uint2 wp;
                wp.x = *(uint32_t*)&wA;
                wp.y = *(uint32_t*)&wB;
                wtab[ebase + t] = wp;
                btab[ebase + t] = (og * HWN + by * 96 + bxm) * 32;
            }
        }
        __syncwarp();
        const __half* qog = g_qog + (size_t)b * 8 * HWN * 32;
        const float* wflat = g_sWt + (size_t)b * 6 * 9 * 128;
        int cb = lane8 * 4;
        float accr[6];
#pragma unroll
        for (int r = 0; r < 6; r++) accr[r] = 0.f;
#pragma unroll 1
        for (int og = 0; og < 8; og++) {
            int cgrp = (og & 3) * 32 + lane8 * 4;
            int rbase = (og < 4) ? 0 : 3;
            int ebase = (pl * 8 + og) * 9;
            float a0 = 0.f, a1 = 0.f, a2 = 0.f;
#pragma unroll
            for (int tap = 0; tap < 9; tap++) {
                uint2 wp = wtab[ebase + tap];
                int base = btab[ebase + tap];
                __half2 hA = *(__half2*)&wp.x;
                __half2 hB = *(__half2*)&wp.y;
                __half2 w00s = __low2half2(hA), w01s = __high2half2(hA);
                __half2 w10s = __low2half2(hB), w11s = __high2half2(hB);
                const __half* cb0 = qog + base + cb;
                uint2 t00 = *(const uint2*)(cb0);
                uint2 t01 = *(const uint2*)(cb0 + 32);
                uint2 t10 = *(const uint2*)(cb0 + 96 * 32);
                uint2 t11 = *(const uint2*)(cb0 + 97 * 32);
                __half2 s0 = __hmul2(w00s, *(__half2*)&t00.x);
                __half2 s1 = __hmul2(w00s, *(__half2*)&t00.y);
                s0 = __hfma2(w01s, *(__half2*)&t01.x, s0);
                s1 = __hfma2(w01s, *(__half2*)&t01.y, s1);
                s0 = __hfma2(w10s, *(__half2*)&t10.x, s0);
                s1 = __hfma2(w10s, *(__half2*)&t10.y, s1);
                s0 = __hfma2(w11s, *(__half2*)&t11.x, s0);
                s1 = __hfma2(w11s, *(__half2*)&t11.y, s1);
                float2 f0 = __half22float2(s0);
                float2 f1 = __half22float2(s1);
                float4 w0 = __ldg((const float4*)&wflat[((rbase + 0) * 9 + tap) * 128 + cgrp]);
                a0 += f0.x * w0.x + f0.y * w0.y + f1.x * w0.z + f1.y * w0.w;
                float4 w1 = __ldg((const float4*)&wflat[((rbase + 1) * 9 + tap) * 128 + cgrp]);
                a1 += f0.x * w1.x + f0.y * w1.y + f1.x * w1.z + f1.y * w1.w;
                float4 w2 = __ldg((const float4*)&wflat[((rbase + 2) * 9 + tap) * 128 + cgrp]);
                a2 += f0.x * w2.x + f0.y * w2.y + f1.x * w2.z + f1.y * w2.w;
            }
            accr[rbase + 0] += a0;
            accr[rbase + 1] += a1;
            accr[rbase + 2] += a2;
        }
#pragma unroll
        for (int r = 0; r < 6; r++) {
            accr[r] += __shfl_xor_sync(0xffffffffu, accr[r], 1);
            accr[r] += __shfl_xor_sync(0xffffffffu, accr[r], 2);
            accr[r] += __shfl_xor_sync(0xffffffffu, accr[r], 4);
        }
        if (lane8 == 0) {
            size_t obase = ((size_t)b * 24 + 6 + dz * 6) * HWN + p;
#pragma unroll
            for (int r = 0; r < 6; r++) g_sim[obase + (size_t)r * HWN] = accr[r];
        }
    } else {
        float* psh = (float*)shbuf;
        int s = bx - 1728;
        int b = s / 288;
        int pg = (s - b * 288) * 32 + pl;
        for (int i = tid; i < 768; i += 256) psh[i] = g_pool[b * 768 + i];
        __syncthreads();
        const __half* qrow = g_qh16 + ((size_t)b * HWN + pg) * 256;
        float acc[6];
#pragma unroll
        for (int r = 0; r < 6; r++) acc[r] = 0.f;
#pragma unroll
        for (int r = 0; r < 6; r++) {
            int g = (r >= 3) ? 1 : 0;
#pragma unroll
            for (int qq = 0; qq < 4; qq++) {
                int f = lane8 + qq * 8;
                uint2 t = *(const uint2*)&qrow[g * 128 + f * 4];
                float2 q0 = __half22float2(*(__half2*)&t.x);
                float2 q1 = __half22float2(*(__half2*)&t.y);
                float4 pv = *(const float4*)&psh[r * 128 + f * 4];
                acc[r] += q0.x * pv.x + q0.y * pv.y + q1.x * pv.z + q1.y * pv.w;
            }
        }
#pragma unroll
        for (int r = 0; r < 6; r++) {
            acc[r] += __shfl_xor_sync(0xffffffffu, acc[r], 1);
            acc[r] += __shfl_xor_sync(0xffffffffu, acc[r], 2);
            acc[r] += __shfl_xor_sync(0xffffffffu, acc[r], 4);
        }
        if (lane8 == 0)
#pragma unroll
            for (int r = 0; r < 6; r++) g_sim[((size_t)b * 24 + r) * HWN + pg] = acc[r];
    }
}

__global__ void outconv_kernel(const float* __restrict__ ow, const float* __restrict__ ob,
                               float* __restrict__ out) {
    __shared__ float ws[256 * 25];
    __shared__ float st[24 * 65];
    int b = blockIdx.y;
    int m0 = blockIdx.x * 64;
    int tid = threadIdx.x;
    for (int i = tid; i < 6144; i += 256) {
        int oc = i / 24, k = i - oc * 24;
        ws[oc * 25 + k] = ow[i];
    }
    for (int i = tid; i < 24 * 64; i += 256) {
        int ch = i >> 6, j = i & 63;
        st[ch * 65 + j] = g_sim[((size_t)b * 24 + ch) * HWN + m0 + j];
    }
    __syncthreads();
    int j = tid & 63;
    int ocb = (tid >> 6) * 64;
    for (int oc = ocb; oc < ocb + 64; oc++) {
        float a = ob[oc];
#pragma unroll
        for (int k = 0; k < 24; k++) a += ws[oc * 25 + k] * st[k * 65 + j];
        out[((size_t)b * 256 + oc) * HWN + m0 + j] = a;
    }
}

extern "C" void kernel_launch(void* const* d_in, const int* in_sizes, int n_in,
                              void* d_out, int out_size) {
    const float* qf = (const float*)d_in[0];
    const float* sf = (const float*)d_in[1];
    const float* in_w = (const float*)d_in[2];
    const float* in_b = (const float*)d_in[3];
    const float* ln_g = (const float*)d_in[4];
    const float* ln_b = (const float*)d_in[5];
    const float* out_w = (const float*)d_in[6];
    const float* out_b = (const float*)d_in[7];
    const float* offw1 = (const float*)d_in[8];
    const float* offb1 = (const float*)d_in[9];
    const float* mskw1 = (const float*)d_in[10];
    const float* mskb1 = (const float*)d_in[11];
    const float* offw2 = (const float*)d_in[12];
    const float* offb2 = (const float*)d_in[13];
    const float* mskw2 = (const float*)d_in[14];
    const float* mskb2 = (const float*)d_in[15];
    const float* offw4 = (const float*)d_in[16];
    const float* offb4 = (const float*)d_in[17];
    const float* mskw4 = (const float*)d_in[18];
    const float* mskb4 = (const float*)d_in[19];
    float* out = (float*)d_out;

    cudaFuncSetAttribute(gemm_in_k, cudaFuncAttributeMaxDynamicSharedMemorySize, SMEM_IN);
    cudaFuncSetAttribute(gemm_big_k, cudaFuncAttributeMaxDynamicSharedMemorySize, SMEM_BIG);
    cudaFuncSetAttribute(deform_sim0, cudaFuncAttributeMaxDynamicSharedMemorySize, SMEM_DEF);

    prep_all<<<695, 256>>>(qf, sf, in_w, in_b, ln_g, ln_b,
                           offw1, mskw1, offw2, mskw2, offw4, mskw4,
                           offb1, mskb1, offb2, mskb2, offb4, mskb4);
    gemm_in_k<<<288, 256, SMEM_IN>>>(in_b, ln_g, ln_b);
    gemm_big_k<<<900, 256, SMEM_BIG>>>();
    deform_sim0<<<2304, 256, SMEM_DEF>>>();
    outconv_kernel<<<dim3(144, 2), 256>>>(out_w, out_b, out);
}

// round 16
// speedup vs baseline: 1.0877x; 1.0877x over previous
#include <cuda_runtime.h>
#include <cuda_fp16.h>
#include <stdint.h>

#define HWN 9216
#define CN 256
#define BB 2
#define NOUT 648
#define CH_BIG 36
#define CH_IN 4
#define NT_BIG 3
#define MT_IN 144
#define BT64 150
#define PADW 98
#define PROWS 9856
#define QROWS 19712
#define RS_BIG 768

__device__ __align__(128) __half g_qpad[(size_t)4 * QROWS * 64];
__device__ __align__(128) __half g_qh16[(size_t)BB * HWN * 256];
__device__ __align__(128) __half g_qog[(size_t)BB * 8 * HWN * 32];
__device__ __align__(128) __half g_Ain[(size_t)MT_IN * CH_IN * 8192];
__device__ __align__(128) __half g_Bbig[(size_t)NT_BIG * CH_BIG * 16384];
__device__ __align__(128) __half g_Bin[(size_t)CH_IN * 16384];
__device__ float g_conv2[(size_t)BB * HWN * RS_BIG];
__device__ float g_sW[BB * 3 * CN * 9];
__device__ float g_pool[BB * 6 * 128];
__device__ float g_sim[BB * 24 * HWN];
__device__ __align__(16) float g_bpack[768];

__device__ __forceinline__ uint32_t smem_u32(const void* p) {
    uint32_t a;
    asm("{ .reg .u64 t; cvta.to.shared.u64 t, %1; cvt.u32.u64 %0, t; }" : "=r"(a) : "l"(p));
    return a;
}
#define MBINIT(a, c) asm volatile("mbarrier.init.shared.b64 [%0], %1;" ::"r"(a), "r"(c) : "memory")
#define MBEXPECT(a, b) \
    asm volatile("mbarrier.arrive.expect_tx.shared.b64 _, [%0], %1;" ::"r"(a), "r"(b) : "memory")
__device__ __forceinline__ void mbar_wait(uint32_t mbar, uint32_t parity) {
    asm volatile(
        "{\n\t.reg .pred P;\n\t"
        "LAB_%=:\n\t"
        "mbarrier.try_wait.parity.acquire.cta.shared::cta.b64 P, [%0], %1, 0x989680;\n\t"
        "@!P bra LAB_%=;\n\t}" ::"r"(mbar), "r"(parity) : "memory");
}
__device__ __forceinline__ void bulk_g2s(uint32_t dst, const void* src, uint32_t bytes, uint32_t mbar) {
    asm volatile(
        "cp.async.bulk.shared::cluster.global.mbarrier::complete_tx::bytes [%0], [%1], %2, [%3];"
        ::"r"(dst), "l"(src), "r"(bytes), "r"(mbar) : "memory");
}
__device__ __forceinline__ void ldsm4(uint32_t* r, uint32_t addr) {
    asm volatile("ldmatrix.sync.aligned.m8n8.x4.shared.b16 {%0,%1,%2,%3}, [%4];"
                 : "=r"(r[0]), "=r"(r[1]), "=r"(r[2]), "=r"(r[3]) : "r"(addr));
}
__device__ __forceinline__ void mma_f16(float* c, const uint32_t* a, const uint32_t* b) {
    asm volatile(
        "mma.sync.aligned.m16n8k16.row.col.f32.f16.f16.f32 "
        "{%0,%1,%2,%3}, {%4,%5,%6,%7}, {%8,%9}, {%0,%1,%2,%3};"
        : "+f"(c[0]), "+f"(c[1]), "+f"(c[2]), "+f"(c[3])
        : "r"(a[0]), "r"(a[1]), "r"(a[2]), "r"(a[3]), "r"(b[0]), "r"(b[1]));
}
__device__ __forceinline__ void cvt8(const float* v, __half* hv) {
#pragma unroll
    for (int j = 0; j < 8; j++) hv[j] = __float2half_rn(v[j]);
}

// ---- merged prep ----
__global__ void prep_all(const float* __restrict__ qf, const float* __restrict__ sup,
                         const float* __restrict__ inw, const float* __restrict__ inb,
                         const float* __restrict__ gam, const float* __restrict__ bet,
                         const float* __restrict__ ow1, const float* __restrict__ mw1,
                         const float* __restrict__ ow2, const float* __restrict__ mw2,
                         const float* __restrict__ ow4, const float* __restrict__ mw4,
                         const float* __restrict__ ob1, const float* __restrict__ mb1,
                         const float* __restrict__ ob2, const float* __restrict__ mb2,
                         const float* __restrict__ ob4, const float* __restrict__ mb4) {
    __shared__ float xs[2304];
    __shared__ float Wt[32 * 257];
    __shared__ float stats[18];
    int bx = blockIdx.x;
    int tid = threadIdx.x;
    if (bx == 0) {
        for (int idx = tid; idx < 768; idx += 256) {
            float v = 0.f;
            if (idx < NOUT) {
                int d = idx / 216, r = idx - d * 216;
                const float* bb = (r < 144) ? (d == 0 ? ob1 : d == 1 ? ob2 : ob4)
                                            : (d == 0 ? mb1 : d == 1 ? mb2 : mb4);
                v = bb[(r < 144) ? r : r - 144];
            }
            g_bpack[idx] = v;
        }
        return;
    }
    if (bx < 5) {
        int chunk = bx - 1;
        int c0 = chunk * 64;
        char* dst = (char*)(g_Bin + (size_t)chunk * 16384);
#pragma unroll
        for (int i = 0; i < 8; i++) {
            int unit = i * 256 + tid;
            int r = unit >> 3, u = unit & 7;
            float v[8];
#pragma unroll
            for (int j = 0; j < 8; j++) v[j] = inw[(size_t)r * 256 + c0 + u * 8 + j];
            __align__(16) __half hv[8];
            cvt8(v, hv);
            uint32_t off = r * 128 + u * 16;
            uint32_t sw = off ^ ((off >> 3) & 0x70);
            *(uint4*)(dst + sw) = *(uint4*)hv;
        }
        return;
    }
    if (bx < 113) {
        int t = bx - 5;
        int nt = t % 3, chunk = t / 3;
        int tap = chunk >> 2;
        int c0 = (chunk & 3) * 64;
        char* dst = (char*)(g_Bbig + (size_t)(nt * CH_BIG + chunk) * 16384);
#pragma unroll
        for (int i = 0; i < 8; i++) {
            int unit = i * 256 + tid;
            int r = unit >> 3, u = unit & 7;
            int n = nt * 256 + r;
            float v[8];
#pragma unroll
            for (int j = 0; j < 8; j++) v[j] = 0.f;
            if (n < NOUT) {
                int d = n / 216, rr = n - d * 216;
                const float* w = (rr < 144) ? (d == 0 ? ow1 : d == 1 ? ow2 : ow4)
                                            : (d == 0 ? mw1 : d == 1 ? mw2 : mw4);
                int oc = (rr < 144) ? rr : rr - 144;
#pragma unroll
                for (int j = 0; j < 8; j++)
                    v[j] = w[(size_t)oc * 2304 + (size_t)(c0 + u * 8 + j) * 9 + tap];
            }
            __align__(16) __half hv[8];
            cvt8(v, hv);
            uint32_t off = r * 128 + u * 16;
            uint32_t sw = off ^ ((off >> 3) & 0x70);
            *(uint4*)(dst + sw) = *(uint4*)hv;
        }
        return;
    }
    if (bx < 689) {
        int t = bx - 113;
        int mt = t % MT_IN, chunk = t / MT_IN;
        int c0 = chunk * 64;
        char* dst = (char*)(g_Ain + (size_t)(mt * CH_IN + chunk) * 8192);
#pragma unroll
        for (int i = 0; i < 4; i++) {
            int unit = i * 256 + tid;
            int r = unit & 127, u = unit >> 7;
            int m = mt * 128 + r;
            int b = m / HWN, p = m - b * HWN;
            float v[8];
#pragma unroll
            for (int j = 0; j < 8; j++) v[j] = qf[((size_t)b * CN + c0 + u * 8 + j) * HWN + p];
            __align__(16) __half hv[8];
            cvt8(v, hv);
            uint32_t off = r * 128 + u * 16;
            uint32_t sw = off ^ ((off >> 3) & 0x70);
            *(uint4*)(dst + sw) = *(uint4*)hv;
        }
        return;
    }
    {
        int bid = bx - 689;
        int b = bid / 3, ex = bid - b * 3;
        const float* sp = sup + (size_t)(b * 3 + ex) * 2304;
        for (int i = tid; i < 2304; i += 256) xs[i] = sp[i];
        float acc[9];
        float bia = inb[tid];
#pragma unroll
        for (int pos = 0; pos < 9; pos++) acc[pos] = bia;
        for (int k0 = 0; k0 < 256; k0 += 32) {
            __syncthreads();
            for (int i = tid; i < 256 * 32; i += 256) {
                int c = i >> 5, kk = i & 31;
                Wt[kk * 257 + c] = inw[(size_t)c * 256 + k0 + kk];
            }
            __syncthreads();
#pragma unroll
            for (int kk = 0; kk < 32; kk++) {
                float w = Wt[kk * 257 + tid];
#pragma unroll
                for (int pos = 0; pos < 9; pos++) acc[pos] += w * xs[(k0 + kk) * 9 + pos];
            }
        }
        __syncthreads();
#pragma unroll
        for (int pos = 0; pos < 9; pos++) xs[tid * 9 + pos] = acc[pos];
        __syncthreads();
        if (tid < 9) {
            float s1 = 0.f, s2 = 0.f;
            for (int c = 0; c < 256; c++) { float v = xs[c * 9 + tid]; s1 += v; s2 += v * v; }
            float mu = s1 * (1.f / 256.f);
            stats[tid] = mu;
            stats[9 + tid] = rsqrtf(s2 * (1.f / 256.f) - mu * mu + 1e-5f);
        }
        __syncthreads();
        float mx = -1e30f;
        float g = gam[tid], be = bet[tid];
#pragma unroll
        for (int pos = 0; pos < 9; pos++) {
            float v = (acc[pos] - stats[pos]) * stats[9 + pos] * g + be;
            g_sW[((size_t)(b * 3 + ex) * 256 + tid) * 9 + pos] = v;
            mx = fmaxf(mx, v);
        }
        int r = ex * 2 + (tid >> 7);
        g_pool[(b * 6 + r) * 128 + (tid & 127)] = mx;
    }
}

// ---- in-projection GEMM (M64, 2-stage, 2 CTA/SM) + fused LN epilogue ----
#define STGI 40960
#define SMEM_IN (1024 + 2 * STGI)
__global__ __launch_bounds__(256, 2) void gemm_in_k(const float* __restrict__ bias,
                                                    const float* __restrict__ gam,
                                                    const float* __restrict__ bet) {
    extern __shared__ char smraw[];
    char* basep = (char*)(((uintptr_t)smraw + 1023) & ~(uintptr_t)1023);
    uint32_t sb = smem_u32(basep);
    int mtg = blockIdx.x;
    int mtH = mtg >> 1, mlo = mtg & 1;
    int tid = threadIdx.x, wid = tid >> 5, lane = tid & 31;
    int wm = (wid & 1) * 32, wn = (wid >> 1) * 64;
    uint32_t FULLB = sb, STG = sb + 1024;
    if (tid == 0)
        for (int s = 0; s < 2; s++) MBINIT(FULLB + s * 8, 1);
    __syncthreads();
    auto issue = [&](int ch, int st) {
        uint32_t S = STG + st * STGI;
        MBEXPECT(FULLB + st * 8, 40960u);
        bulk_g2s(S, g_Ain + (size_t)(mtH * CH_IN + ch) * 8192 + mlo * 4096, 8192u, FULLB + st * 8);
        bulk_g2s(S + 8192, g_Bin + (size_t)ch * 16384, 32768u, FULLB + st * 8);
    };
    if (tid == 0) { issue(0, 0); issue(1, 1); }
    float acc[2][8][4];
#pragma unroll
    for (int a = 0; a < 2; a++)
#pragma unroll
        for (int n = 0; n < 8; n++)
#pragma unroll
            for (int c = 0; c < 4; c++) acc[a][n][c] = 0.f;
    int x7 = lane & 7, kuA = lane >> 4, kuB = (lane >> 3) & 1;
    uint32_t offA[2], offB[4];
#pragma unroll
    for (int mt2 = 0; mt2 < 2; mt2++)
        offA[mt2] = (uint32_t)(wm + mt2 * 16 + ((lane >> 3) & 1) * 8 + x7) * 128u;
#pragma unroll
    for (int ng = 0; ng < 4; ng++)
        offB[ng] = (uint32_t)(wn + ng * 16 + ((lane >> 4) << 3) + x7) * 128u;
    for (int ch = 0; ch < CH_IN; ch++) {
        int st = ch & 1;
        mbar_wait(FULLB + st * 8, (uint32_t)((ch >> 1) & 1));
        uint32_t aB = STG + st * STGI, bB = aB + 8192;
#pragma unroll
        for (int ks = 0; ks < 4; ks++) {
            uint32_t cA = (uint32_t)(((ks * 2 + kuA) ^ x7) << 4);
            uint32_t cB = (uint32_t)(((ks * 2 + kuB) ^ x7) << 4);
            uint32_t Ah[2][4];
#pragma unroll
            for (int mt2 = 0; mt2 < 2; mt2++) ldsm4(Ah[mt2], aB + offA[mt2] + cA);
#pragma unroll
            for (int ng = 0; ng < 4; ng++) {
                uint32_t Bh[4];
                ldsm4(Bh, bB + offB[ng] + cB);
#pragma unroll
                for (int h = 0; h < 2; h++) {
                    int n8 = ng * 2 + h;
                    mma_f16(acc[0][n8], Ah[0], &Bh[h * 2]);
                    mma_f16(acc[1][n8], Ah[1], &Bh[h * 2]);
                }
            }
        }
        __syncthreads();
        if (tid == 0 && ch + 2 < CH_IN) issue(ch + 2, st);
    }
    float* tile = (float*)(basep + 1024);
#pragma unroll
    for (int mt2 = 0; mt2 < 2; mt2++)
#pragma unroll
        for (int half = 0; half < 2; half++) {
            int r = wm + mt2 * 16 + (lane >> 2) + half * 8;
            float* trow = tile + (size_t)r * 264;
#pragma unroll
            for (int n8 = 0; n8 < 8; n8++) {
                int col = wn + n8 * 8 + (lane & 3) * 2;
                float2 v = make_float2(acc[mt2][n8][half * 2 + 0] + bias[col],
                                       acc[mt2][n8][half * 2 + 1] + bias[col + 1]);
                *(float2*)&trow[col] = v;
            }
        }
    __syncthreads();
    float gv[8], bv[8];
#pragma unroll
    for (int j = 0; j < 8; j++) {
        int c = lane * 8 + j;
        gv[j] = __ldg(&gam[c]);
        bv[j] = __ldg(&bet[c]);
    }
    for (int rr = 0; rr < 8; rr++) {
        int row = wid * 8 + rr;
        const float* trow = tile + (size_t)row * 264 + lane * 8;
        float4 a = *(const float4*)trow;
        float4 b4 = *(const float4*)(trow + 4);
        float v[8] = {a.x, a.y, a.z, a.w, b4.x, b4.y, b4.z, b4.w};
        float s1 = 0.f, s2 = 0.f;
#pragma unroll
        for (int j = 0; j < 8; j++) { s1 += v[j]; s2 += v[j] * v[j]; }
#pragma unroll
        for (int o = 16; o > 0; o >>= 1) {
            s1 += __shfl_xor_sync(0xffffffffu, s1, o);
            s2 += __shfl_xor_sync(0xffffffffu, s2, o);
        }
        float mu = s1 * (1.f / 256.f);
        float rv = rsqrtf(s2 * (1.f / 256.f) - mu * mu + 1e-5f);
#pragma unroll
        for (int j = 0; j < 8; j++) v[j] = (v[j] - mu) * rv * gv[j] + bv[j];
        __align__(16) __half hv[8];
        cvt8(v, hv);
        int m = mtg * 64 + row;
        *(uint4*)&g_qh16[(size_t)m * 256 + lane * 8] = *(uint4*)hv;
        int b = m / HWN, p = m - b * HWN;
        {
            int og = lane >> 2, chin = (lane & 3) * 8;
            *(uint4*)&g_qog[(((size_t)(b * 8 + og)) * HWN + p) * 32 + chin] = *(uint4*)hv;
        }
        int y = p / 96, x = p - y * 96;
        size_t r_abs = (size_t)b * PROWS + 128 + (size_t)(y + 1) * PADW + (x + 1);
        int cq = lane >> 3, u = lane & 7;
        uint32_t sw = (uint32_t)(u * 16) ^ (((uint32_t)r_abs & 7) << 4);
        char* hb = (char*)(g_qpad + ((size_t)cq * QROWS + r_abs) * 64);
        *(uint4*)(hb + sw) = *(uint4*)hv;
    }
}

// ---- big conv GEMM ----
#define STGB 40960
#define SMEM_BIG (1024 + 2 * STGB)
__global__ __launch_bounds__(256, 2) void gemm_big_k() {
    extern __shared__ char smraw[];
    char* basep = (char*)(((uintptr_t)smraw + 1023) & ~(uintptr_t)1023);
    uint32_t sb = smem_u32(basep);
    int bx = blockIdx.x;
    int mtg = bx / 3, nt = bx - mtg * 3;
    int b = mtg / BT64, mt_local = mtg - b * BT64;
    size_t arowbase = (size_t)b * PROWS + 128 + (size_t)mt_local * 64;
    int tid = threadIdx.x, wid = tid >> 5, lane = tid & 31;
    int wm = (wid & 1) * 32, wn = (wid >> 1) * 64;
    int ngm = 4;
    if (nt == 2) ngm = (wn == 128) ? 1 : (wn == 192) ? 0 : 4;
    uint32_t FULLB = sb, STG = sb + 1024;
    if (tid == 0)
        for (int s = 0; s < 2; s++) MBINIT(FULLB + s * 8, 1);
    __syncthreads();
    auto issue = [&](int ch, int st) {
        uint32_t S = STG + st * STGB;
        MBEXPECT(FULLB + st * 8, 40960u);
        int tap = ch >> 2, cq = ch & 3;
        int shift = (tap / 3 - 1) * PADW + (tap % 3 - 1);
        size_t row0 = arowbase + shift;
        bulk_g2s(S, g_qpad + ((size_t)cq * QROWS + row0) * 64, 8192u, FULLB + st * 8);
        bulk_g2s(S + 8192, g_Bbig + (size_t)(nt * CH_BIG + ch) * 16384, 32768u, FULLB + st * 8);
    };
    if (tid == 0) { issue(0, 0); issue(1, 1); }
    float acc[2][8][4];
#pragma unroll
    for (int a = 0; a < 2; a++)
#pragma unroll
        for (int n = 0; n < 8; n++)
#pragma unroll
            for (int c = 0; c < 4; c++) acc[a][n][c] = 0.f;
    int x7 = lane & 7, kuA = lane >> 4, kuB = (lane >> 3) & 1;
    uint32_t offA[2], offB[4];
#pragma unroll
    for (int mt2 = 0; mt2 < 2; mt2++)
        offA[mt2] = (uint32_t)(wm + mt2 * 16 + ((lane >> 3) & 1) * 8 + x7) * 128u;
#pragma unroll
    for (int ng = 0; ng < 4; ng++)
        offB[ng] = (uint32_t)(wn + ng * 16 + ((lane >> 4) << 3) + x7) * 128u;
    for (int ch = 0; ch < CH_BIG; ch++) {
        int st = ch & 1;
        mbar_wait(FULLB + st * 8, (uint32_t)((ch >> 1) & 1));
        uint32_t aB = STG + st * STGB, bB = aB + 8192;
        int tap = ch >> 2;
        int shift = (tap / 3 - 1) * PADW + (tap % 3 - 1);
        int xA = (x7 + shift) & 7;
        if (ngm == 4) {
#pragma unroll
            for (int ks = 0; ks < 4; ks++) {
                uint32_t cA = (uint32_t)(((ks * 2 + kuA) ^ xA) << 4);
                uint32_t cB = (uint32_t)(((ks * 2 + kuB) ^ x7) << 4);
                uint32_t Ah[2][4];
#pragma unroll
                for (int mt2 = 0; mt2 < 2; mt2++) ldsm4(Ah[mt2], aB + offA[mt2] + cA);
#pragma unroll
                for (int ng = 0; ng < 4; ng++) {
                    uint32_t Bh[4];
                    ldsm4(Bh, bB + offB[ng] + cB);
#pragma unroll
                    for (int h = 0; h < 2; h++) {
                        int n8 = ng * 2 + h;
                        mma_f16(acc[0][n8], Ah[0], &Bh[h * 2]);
                        mma_f16(acc[1][n8], Ah[1], &Bh[h * 2]);
                    }
                }
            }
        } else if (ngm == 1) {
#pragma unroll
            for (int ks = 0; ks < 4; ks++) {
                uint32_t cA = (uint32_t)(((ks * 2 + kuA) ^ xA) << 4);
                uint32_t cB = (uint32_t)(((ks * 2 + kuB) ^ x7) << 4);
                uint32_t Ah[2][4];
#pragma unroll
                for (int mt2 = 0; mt2 < 2; mt2++) ldsm4(Ah[mt2], aB + offA[mt2] + cA);
                uint32_t Bh[4];
                ldsm4(Bh, bB + offB[0] + cB);
#pragma unroll
                for (int h = 0; h < 2; h++) {
                    mma_f16(acc[0][h], Ah[0], &Bh[h * 2]);
                    mma_f16(acc[1][h], Ah[1], &Bh[h * 2]);
                }
            }
        }
        __syncthreads();
        if (tid == 0 && ch + 2 < CH_BIG) issue(ch + 2, st);
    }
#pragma unroll
    for (int mt2 = 0; mt2 < 2; mt2++)
#pragma unroll
        for (int half = 0; half < 2; half++) {
            int r = wm + mt2 * 16 + (lane >> 2) + half * 8;
            int pp = mt_local * 64 + r;
            int yq = pp / PADW, xq = pp - yq * PADW;
            bool ok = (yq >= 1) && (yq <= 96) && (xq >= 1) && (xq <= 96);
            if (!ok) continue;
            float* drow = g_conv2 + ((size_t)(b * HWN + (yq - 1) * 96 + xq - 1)) * RS_BIG;
#pragma unroll
            for (int n8 = 0; n8 < 8; n8++) {
                int col = nt * 256 + wn + n8 * 8 + (lane & 3) * 2;
                float2 v = make_float2(acc[mt2][n8][half * 2 + 0] + g_bpack[col],
                                       acc[mt2][n8][half * 2 + 1] + g_bpack[col + 1]);
                *(float2*)&drow[col] = v;
            }
        }
}

// ---- deform + sim0: fp16 weight staging (LDS.64), 41.5 KB smem ----
// smem: wshh half[6912]@0 (13824) | wtab uint2[2304]@13824 (18432) | btab int[2304]@32256 (9216)
#define SMEM_DEF 41472
__global__ void deform_sim0() {
    extern __shared__ char shbuf[];
    int bx = blockIdx.x;
    int tid = threadIdx.x;
    int lane8 = tid & 7, pl = tid >> 3;
    if (bx < 1728) {
        __half* wshh = (__half*)shbuf;
        uint2* wtab = (uint2*)(shbuf + 13824);
        int* btab = (int*)(shbuf + 32256);
        int i0 = bx % 12;
        int rest = bx / 12;
        int j0 = rest % 24;
        int z = rest / 24;
        int b = z / 3, dz = z - b * 3;
        int dil = 1 << dz;
        int px = i0 * 8 + (pl & 7);
        int py = j0 * 4 + (pl >> 3);
        int p = py * 96 + px;
        for (int i = tid; i < 6912; i += 256) {
            int r = i / 1152;
            int rem = i - r * 1152;
            int tap = rem >> 7;
            int cg = rem & 127;
            int ex = r >> 1, half = r & 1;
            wshh[i] = __float2half_rn(
                g_sW[((size_t)(b * 3 + ex) * 256 + half * 128 + cg) * 9 + tap]);
        }
        const float* prow = g_conv2 + ((size_t)(b * HWN) + p) * RS_BIG + dz * 216;
        {
            const float* mrow = prow + 144;
            float vals[9];
            float mx = -1e30f;
#pragma unroll
            for (int t = 0; t < 9; t++) {
                vals[t] = __ldg(&mrow[lane8 * 9 + t]);
                mx = fmaxf(mx, vals[t]);
            }
            mx = fmaxf(mx, __shfl_xor_sync(0xffffffffu, mx, 1));
            mx = fmaxf(mx, __shfl_xor_sync(0xffffffffu, mx, 2));
            mx = fmaxf(mx, __shfl_xor_sync(0xffffffffu, mx, 4));
            float s = 0.f;
#pragma unroll
            for (int t = 0; t < 9; t++) { vals[t] = __expf(vals[t] - mx); s += vals[t]; }
            s += __shfl_xor_sync(0xffffffffu, s, 1);
            s += __shfl_xor_sync(0xffffffffu, s, 2);
            s += __shfl_xor_sync(0xffffffffu, s, 4);
            float inv = 1.f / s;
            int og = lane8;
            int ebase = (pl * 8 + og) * 9;
#pragma unroll
            for (int t = 0; t < 9; t++) {
                float m = vals[t] * inv;
                float dy = __ldg(&prow[og * 18 + t * 2]);
                float dx = __ldg(&prow[og * 18 + t * 2 + 1]);
                float fy = (float)(py + (t / 3) * dil - dil) + dy;
                float fx = (float)(px + (t % 3) * dil - dil) + dx;
                int y0 = (int)floorf(fy), x0 = (int)floorf(fx);
                int by = min(max(y0, 0), 94), bxm = min(max(x0, 0), 94);
                float wy0 = fmaxf(0.f, 1.f - fabsf(fy - (float)by));
                float wy1 = fmaxf(0.f, 1.f - fabsf(fy - (float)(by + 1)));
                float wx0 = fmaxf(0.f, 1.f - fabsf(fx - (float)bxm));
                float wx1 = fmaxf(0.f, 1.f - fabsf(fx - (float)(bxm + 1)));
                __half2 wA = __floats2half2_rn(wy0 * wx0 * m, wy0 * wx1 * m);
                __half2 wB = __floats2half2_rn(wy1 * wx0 * m, wy1 * wx1 * m);
                uint2 wp;
                wp.x = *(uint32_t*)&wA;
                wp.y = *(uint32_t*)&wB;
                wtab[ebase + t] = wp;
                btab[ebase + t] = (og * HWN + by * 96 + bxm) * 32;
            }
        }
        __syncthreads();
        const __half* qog = g_qog + (size_t)b * 8 * HWN * 32;
        int cb = lane8 * 4;
        float accr[6];
#pragma unroll
        for (int r = 0; r < 6; r++) accr[r] = 0.f;
#pragma unroll 1
        for (int og = 0; og < 8; og++) {
            int cgrp = (og & 3) * 32 + lane8 * 4;
            int rbase = (og < 4) ? 0 : 3;
            int ebase = (pl * 8 + og) * 9;
            float a0 = 0.f, a1 = 0.f, a2 = 0.f;
#pragma unroll
            for (int tap = 0; tap < 9; tap++) {
                uint2 wp = wtab[ebase + tap];
                int base = btab[ebase + tap];
                __half2 hA = *(__half2*)&wp.x;
                __half2 hB = *(__half2*)&wp.y;
                __half2 w00s = __low2half2(hA), w01s = __high2half2(hA);
                __half2 w10s = __low2half2(hB), w11s = __high2half2(hB);
                const __half* cb0 = qog + base + cb;
                uint2 t00 = *(const uint2*)(cb0);
                uint2 t01 = *(const uint2*)(cb0 + 32);
                uint2 t10 = *(const uint2*)(cb0 + 96 * 32);
                uint2 t11 = *(const uint2*)(cb0 + 97 * 32);
                __half2 s0 = __hmul2(w00s, *(__half2*)&t00.x);
                __half2 s1 = __hmul2(w00s, *(__half2*)&t00.y);
                s0 = __hfma2(w01s, *(__half2*)&t01.x, s0);
                s1 = __hfma2(w01s, *(__half2*)&t01.y, s1);
                s0 = __hfma2(w10s, *(__half2*)&t10.x, s0);
                s1 = __hfma2(w10s, *(__half2*)&t10.y, s1);
                s0 = __hfma2(w11s, *(__half2*)&t11.x, s0);
                s1 = __hfma2(w11s, *(__half2*)&t11.y, s1);
                float2 f0 = __half22float2(s0);
                float2 f1 = __half22float2(s1);
                uint2 wv0 = *(const uint2*)&wshh[((rbase + 0) * 9 + tap) * 128 + cgrp];
                float2 wa0 = __half22float2(*(__half2*)&wv0.x);
                float2 wb0 = __half22float2(*(__half2*)&wv0.y);
                a0 += f0.x * wa0.x + f0.y * wa0.y + f1.x * wb0.x + f1.y * wb0.y;
                uint2 wv1 = *(const uint2*)&wshh[((rbase + 1) * 9 + tap) * 128 + cgrp];
                float2 wa1 = __half22float2(*(__half2*)&wv1.x);
                float2 wb1 = __half22float2(*(__half2*)&wv1.y);
                a1 += f0.x * wa1.x + f0.y * wa1.y + f1.x * wb1.x + f1.y * wb1.y;
                uint2 wv2 = *(const uint2*)&wshh[((rbase + 2) * 9 + tap) * 128 + cgrp];
                float2 wa2 = __half22float2(*(__half2*)&wv2.x);
                float2 wb2 = __half22float2(*(__half2*)&wv2.y);
                a2 += f0.x * wa2.x + f0.y * wa2.y + f1.x * wb2.x + f1.y * wb2.y;
            }
            accr[rbase + 0] += a0;
            accr[rbase + 1] += a1;
            accr[rbase + 2] += a2;
        }
#pragma unroll
        for (int r = 0; r < 6; r++) {
            accr[r] += __shfl_xor_sync(0xffffffffu, accr[r], 1);
            accr[r] += __shfl_xor_sync(0xffffffffu, accr[r], 2);
            accr[r] += __shfl_xor_sync(0xffffffffu, accr[r], 4);
        }
        if (lane8 == 0) {
            size_t obase = ((size_t)b * 24 + 6 + dz * 6) * HWN + p;
#pragma unroll
            for (int r = 0; r < 6; r++) g_sim[obase + (size_t)r * HWN] = accr[r];
        }
    } else {
        float* psh = (float*)shbuf;
        int s = bx - 1728;
        int b = s / 288;
        int pg = (s - b * 288) * 32 + pl;
        for (int i = tid; i < 768; i += 256) psh[i] = g_pool[b * 768 + i];
        __syncthreads();
        const __half* qrow = g_qh16 + ((size_t)b * HWN + pg) * 256;
        float acc[6];
#pragma unroll
        for (int r = 0; r < 6; r++) acc[r] = 0.f;
#pragma unroll
        for (int r = 0; r < 6; r++) {
            int g = (r >= 3) ? 1 : 0;
#pragma unroll
            for (int qq = 0; qq < 4; qq++) {
                int f = lane8 + qq * 8;
                uint2 t = *(const uint2*)&qrow[g * 128 + f * 4];
                float2 q0 = __half22float2(*(__half2*)&t.x);
                float2 q1 = __half22float2(*(__half2*)&t.y);
                float4 pv = *(const float4*)&psh[r * 128 + f * 4];
                acc[r] += q0.x * pv.x + q0.y * pv.y + q1.x * pv.z + q1.y * pv.w;
            }
        }
#pragma unroll
        for (int r = 0; r < 6; r++) {
            acc[r] += __shfl_xor_sync(0xffffffffu, acc[r], 1);
            acc[r] += __shfl_xor_sync(0xffffffffu, acc[r], 2);
            acc[r] += __shfl_xor_sync(0xffffffffu, acc[r], 4);
        }
        if (lane8 == 0)
#pragma unroll
            for (int r = 0; r < 6; r++) g_sim[((size_t)b * 24 + r) * HWN + pg] = acc[r];
    }
}

__global__ void outconv_kernel(const float* __restrict__ ow, const float* __restrict__ ob,
                               float* __restrict__ out) {
    __shared__ float ws[256 * 25];
    __shared__ float st[24 * 65];
    int b = blockIdx.y;
    int m0 = blockIdx.x * 64;
    int tid = threadIdx.x;
    for (int i = tid; i < 6144; i += 256) {
        int oc = i / 24, k = i - oc * 24;
        ws[oc * 25 + k] = ow[i];
    }
    for (int i = tid; i < 24 * 64; i += 256) {
        int ch = i >> 6, j = i & 63;
        st[ch * 65 + j] = g_sim[((size_t)b * 24 + ch) * HWN + m0 + j];
    }
    __syncthreads();
    int j = tid & 63;
    int ocb = (tid >> 6) * 64;
    for (int oc = ocb; oc < ocb + 64; oc++) {
        float a = ob[oc];
#pragma unroll
        for (int k = 0; k < 24; k++) a += ws[oc * 25 + k] * st[k * 65 + j];
        out[((size_t)b * 256 + oc) * HWN + m0 + j] = a;
    }
}

extern "C" void kernel_launch(void* const* d_in, const int* in_sizes, int n_in,
                              void* d_out, int out_size) {
    const float* qf = (const float*)d_in[0];
    const float* sf = (const float*)d_in[1];
    const float* in_w = (const float*)d_in[2];
    const float* in_b = (const float*)d_in[3];
    const float* ln_g = (const float*)d_in[4];
    const float* ln_b = (const float*)d_in[5];
    const float* out_w = (const float*)d_in[6];
    const float* out_b = (const float*)d_in[7];
    const float* offw1 = (const float*)d_in[8];
    const float* offb1 = (const float*)d_in[9];
    const float* mskw1 = (const float*)d_in[10];
    const float* mskb1 = (const float*)d_in[11];
    const float* offw2 = (const float*)d_in[12];
    const float* offb2 = (const float*)d_in[13];
    const float* mskw2 = (const float*)d_in[14];
    const float* mskb2 = (const float*)d_in[15];
    const float* offw4 = (const float*)d_in[16];
    const float* offb4 = (const float*)d_in[17];
    const float* mskw4 = (const float*)d_in[18];
    const float* mskb4 = (const float*)d_in[19];
    float* out = (float*)d_out;

    cudaFuncSetAttribute(gemm_in_k, cudaFuncAttributeMaxDynamicSharedMemorySize, SMEM_IN);
    cudaFuncSetAttribute(gemm_big_k, cudaFuncAttributeMaxDynamicSharedMemorySize, SMEM_BIG);
    cudaFuncSetAttribute(deform_sim0, cudaFuncAttributeMaxDynamicSharedMemorySize, SMEM_DEF);

    prep_all<<<695, 256>>>(qf, sf, in_w, in_b, ln_g, ln_b,
                           offw1, mskw1, offw2, mskw2, offw4, mskw4,
                           offb1, mskb1, offb2, mskb2, offb4, mskb4);
    gemm_in_k<<<288, 256, SMEM_IN>>>(in_b, ln_g, ln_b);
    gemm_big_k<<<900, 256, SMEM_BIG>>>();
    deform_sim0<<<2304, 256, SMEM_DEF>>>();
    outconv_kernel<<<dim3(144, 2), 256>>>(out_w, out_b, out);
}

// round 17
// speedup vs baseline: 1.1393x; 1.0475x over previous
#include <cuda_runtime.h>
#include <cuda_fp16.h>
#include <stdint.h>

#define HWN 9216
#define CN 256
#define BB 2
#define NOUT 648
#define CH_BIG 36
#define CH_IN 4
#define NT_BIG 3
#define MT_IN 144
#define BT64 150
#define PADW 98
#define PROWS 9856
#define QROWS 19712
#define RS_BIG 768

__device__ __align__(128) __half g_qpad[(size_t)4 * QROWS * 64];
__device__ __align__(128) __half g_qh16[(size_t)BB * HWN * 256];
__device__ __align__(128) __half g_qog[(size_t)BB * 8 * HWN * 32];
__device__ __align__(128) __half g_Ain[(size_t)MT_IN * CH_IN * 8192];
__device__ __align__(128) __half g_Bbig[(size_t)NT_BIG * CH_BIG * 16384];
__device__ __align__(128) __half g_Bin[(size_t)CH_IN * 16384];
__device__ float g_conv2[(size_t)BB * HWN * RS_BIG];
__device__ float g_sW[BB * 3 * CN * 9];
__device__ float g_pool[BB * 6 * 128];
__device__ float g_sim[BB * 24 * HWN];
__device__ __align__(16) float g_bpack[768];

__device__ __forceinline__ uint32_t smem_u32(const void* p) {
    uint32_t a;
    asm("{ .reg .u64 t; cvta.to.shared.u64 t, %1; cvt.u32.u64 %0, t; }" : "=r"(a) : "l"(p));
    return a;
}
#define MBINIT(a, c) asm volatile("mbarrier.init.shared.b64 [%0], %1;" ::"r"(a), "r"(c) : "memory")
#define MBEXPECT(a, b) \
    asm volatile("mbarrier.arrive.expect_tx.shared.b64 _, [%0], %1;" ::"r"(a), "r"(b) : "memory")
__device__ __forceinline__ void mbar_wait(uint32_t mbar, uint32_t parity) {
    asm volatile(
        "{\n\t.reg .pred P;\n\t"
        "LAB_%=:\n\t"
        "mbarrier.try_wait.parity.acquire.cta.shared::cta.b64 P, [%0], %1, 0x989680;\n\t"
        "@!P bra LAB_%=;\n\t}" ::"r"(mbar), "r"(parity) : "memory");
}
__device__ __forceinline__ void bulk_g2s(uint32_t dst, const void* src, uint32_t bytes, uint32_t mbar) {
    asm volatile(
        "cp.async.bulk.shared::cluster.global.mbarrier::complete_tx::bytes [%0], [%1], %2, [%3];"
        ::"r"(dst), "l"(src), "r"(bytes), "r"(mbar) : "memory");
}
__device__ __forceinline__ void ldsm4(uint32_t* r, uint32_t addr) {
    asm volatile("ldmatrix.sync.aligned.m8n8.x4.shared.b16 {%0,%1,%2,%3}, [%4];"
                 : "=r"(r[0]), "=r"(r[1]), "=r"(r[2]), "=r"(r[3]) : "r"(addr));
}
__device__ __forceinline__ void mma_f16(float* c, const uint32_t* a, const uint32_t* b) {
    asm volatile(
        "mma.sync.aligned.m16n8k16.row.col.f32.f16.f16.f32 "
        "{%0,%1,%2,%3}, {%4,%5,%6,%7}, {%8,%9}, {%0,%1,%2,%3};"
        : "+f"(c[0]), "+f"(c[1]), "+f"(c[2]), "+f"(c[3])
        : "r"(a[0]), "r"(a[1]), "r"(a[2]), "r"(a[3]), "r"(b[0]), "r"(b[1]));
}
__device__ __forceinline__ void cvt8(const float* v, __half* hv) {
#pragma unroll
    for (int j = 0; j < 8; j++) hv[j] = __float2half_rn(v[j]);
}

// ---- merged prep ----
__global__ void prep_all(const float* __restrict__ qf, const float* __restrict__ sup,
                         const float* __restrict__ inw, const float* __restrict__ inb,
                         const float* __restrict__ gam, const float* __restrict__ bet,
                         const float* __restrict__ ow1, const float* __restrict__ mw1,
                         const float* __restrict__ ow2, const float* __restrict__ mw2,
                         const float* __restrict__ ow4, const float* __restrict__ mw4,
                         const float* __restrict__ ob1, const float* __restrict__ mb1,
                         const float* __restrict__ ob2, const float* __restrict__ mb2,
                         const float* __restrict__ ob4, const float* __restrict__ mb4) {
    __shared__ float xs[2304];
    __shared__ float Wt[32 * 257];
    __shared__ float stats[18];
    int bx = blockIdx.x;
    int tid = threadIdx.x;
    if (bx == 0) {
        for (int idx = tid; idx < 768; idx += 256) {
            float v = 0.f;
            if (idx < NOUT) {
                int d = idx / 216, r = idx - d * 216;
                const float* bb = (r < 144) ? (d == 0 ? ob1 : d == 1 ? ob2 : ob4)
                                            : (d == 0 ? mb1 : d == 1 ? mb2 : mb4);
                v = bb[(r < 144) ? r : r - 144];
            }
            g_bpack[idx] = v;
        }
        return;
    }
    if (bx < 5) {
        int chunk = bx - 1;
        int c0 = chunk * 64;
        char* dst = (char*)(g_Bin + (size_t)chunk * 16384);
#pragma unroll
        for (int i = 0; i < 8; i++) {
            int unit = i * 256 + tid;
            int r = unit >> 3, u = unit & 7;
            float v[8];
#pragma unroll
            for (int j = 0; j < 8; j++) v[j] = inw[(size_t)r * 256 + c0 + u * 8 + j];
            __align__(16) __half hv[8];
            cvt8(v, hv);
            uint32_t off = r * 128 + u * 16;
            uint32_t sw = off ^ ((off >> 3) & 0x70);
            *(uint4*)(dst + sw) = *(uint4*)hv;
        }
        return;
    }
    if (bx < 113) {
        int t = bx - 5;
        int nt = t % 3, chunk = t / 3;
        int tap = chunk >> 2;
        int c0 = (chunk & 3) * 64;
        char* dst = (char*)(g_Bbig + (size_t)(nt * CH_BIG + chunk) * 16384);
#pragma unroll
        for (int i = 0; i < 8; i++) {
            int unit = i * 256 + tid;
            int r = unit >> 3, u = unit & 7;
            int n = nt * 256 + r;
            float v[8];
#pragma unroll
            for (int j = 0; j < 8; j++) v[j] = 0.f;
            if (n < NOUT) {
                int d = n / 216, rr = n - d * 216;
                const float* w = (rr < 144) ? (d == 0 ? ow1 : d == 1 ? ow2 : ow4)
                                            : (d == 0 ? mw1 : d == 1 ? mw2 : mw4);
                int oc = (rr < 144) ? rr : rr - 144;
#pragma unroll
                for (int j = 0; j < 8; j++)
                    v[j] = w[(size_t)oc * 2304 + (size_t)(c0 + u * 8 + j) * 9 + tap];
            }
            __align__(16) __half hv[8];
            cvt8(v, hv);
            uint32_t off = r * 128 + u * 16;
            uint32_t sw = off ^ ((off >> 3) & 0x70);
            *(uint4*)(dst + sw) = *(uint4*)hv;
        }
        return;
    }
    if (bx < 689) {
        int t = bx - 113;
        int mt = t % MT_IN, chunk = t / MT_IN;
        int c0 = chunk * 64;
        char* dst = (char*)(g_Ain + (size_t)(mt * CH_IN + chunk) * 8192);
#pragma unroll
        for (int i = 0; i < 4; i++) {
            int unit = i * 256 + tid;
            int r = unit & 127, u = unit >> 7;
            int m = mt * 128 + r;
            int b = m / HWN, p = m - b * HWN;
            float v[8];
#pragma unroll
            for (int j = 0; j < 8; j++) v[j] = qf[((size_t)b * CN + c0 + u * 8 + j) * HWN + p];
            __align__(16) __half hv[8];
            cvt8(v, hv);
            uint32_t off = r * 128 + u * 16;
            uint32_t sw = off ^ ((off >> 3) & 0x70);
            *(uint4*)(dst + sw) = *(uint4*)hv;
        }
        return;
    }
    {
        int bid = bx - 689;
        int b = bid / 3, ex = bid - b * 3;
        const float* sp = sup + (size_t)(b * 3 + ex) * 2304;
        for (int i = tid; i < 2304; i += 256) xs[i] = sp[i];
        float acc[9];
        float bia = inb[tid];
#pragma unroll
        for (int pos = 0; pos < 9; pos++) acc[pos] = bia;
        for (int k0 = 0; k0 < 256; k0 += 32) {
            __syncthreads();
            for (int i = tid; i < 256 * 32; i += 256) {
                int c = i >> 5, kk = i & 31;
                Wt[kk * 257 + c] = inw[(size_t)c * 256 + k0 + kk];
            }
            __syncthreads();
#pragma unroll
            for (int kk = 0; kk < 32; kk++) {
                float w = Wt[kk * 257 + tid];
#pragma unroll
                for (int pos = 0; pos < 9; pos++) acc[pos] += w * xs[(k0 + kk) * 9 + pos];
            }
        }
        __syncthreads();
#pragma unroll
        for (int pos = 0; pos < 9; pos++) xs[tid * 9 + pos] = acc[pos];
        __syncthreads();
        if (tid < 9) {
            float s1 = 0.f, s2 = 0.f;
            for (int c = 0; c < 256; c++) { float v = xs[c * 9 + tid]; s1 += v; s2 += v * v; }
            float mu = s1 * (1.f / 256.f);
            stats[tid] = mu;
            stats[9 + tid] = rsqrtf(s2 * (1.f / 256.f) - mu * mu + 1e-5f);
        }
        __syncthreads();
        float mx = -1e30f;
        float g = gam[tid], be = bet[tid];
#pragma unroll
        for (int pos = 0; pos < 9; pos++) {
            float v = (acc[pos] - stats[pos]) * stats[9 + pos] * g + be;
            g_sW[((size_t)(b * 3 + ex) * 256 + tid) * 9 + pos] = v;
            mx = fmaxf(mx, v);
        }
        int r = ex * 2 + (tid >> 7);
        g_pool[(b * 6 + r) * 128 + (tid & 127)] = mx;
    }
}

// ---- in-projection GEMM (M64, 2-stage, 2 CTA/SM) + fused LN epilogue ----
#define STGI 40960
#define SMEM_IN (1024 + 2 * STGI)
__global__ __launch_bounds__(256, 2) void gemm_in_k(const float* __restrict__ bias,
                                                    const float* __restrict__ gam,
                                                    const float* __restrict__ bet) {
    extern __shared__ char smraw[];
    char* basep = (char*)(((uintptr_t)smraw + 1023) & ~(uintptr_t)1023);
    uint32_t sb = smem_u32(basep);
    int mtg = blockIdx.x;
    int mtH = mtg >> 1, mlo = mtg & 1;
    int tid = threadIdx.x, wid = tid >> 5, lane = tid & 31;
    int wm = (wid & 1) * 32, wn = (wid >> 1) * 64;
    uint32_t FULLB = sb, STG = sb + 1024;
    if (tid == 0)
        for (int s = 0; s < 2; s++) MBINIT(FULLB + s * 8, 1);
    __syncthreads();
    auto issue = [&](int ch, int st) {
        uint32_t S = STG + st * STGI;
        MBEXPECT(FULLB + st * 8, 40960u);
        bulk_g2s(S, g_Ain + (size_t)(mtH * CH_IN + ch) * 8192 + mlo * 4096, 8192u, FULLB + st * 8);
        bulk_g2s(S + 8192, g_Bin + (size_t)ch * 16384, 32768u, FULLB + st * 8);
    };
    if (tid == 0) { issue(0, 0); issue(1, 1); }
    float acc[2][8][4];
#pragma unroll
    for (int a = 0; a < 2; a++)
#pragma unroll
        for (int n = 0; n < 8; n++)
#pragma unroll
            for (int c = 0; c < 4; c++) acc[a][n][c] = 0.f;
    int x7 = lane & 7, kuA = lane >> 4, kuB = (lane >> 3) & 1;
    uint32_t offA[2], offB[4];
#pragma unroll
    for (int mt2 = 0; mt2 < 2; mt2++)
        offA[mt2] = (uint32_t)(wm + mt2 * 16 + ((lane >> 3) & 1) * 8 + x7) * 128u;
#pragma unroll
    for (int ng = 0; ng < 4; ng++)
        offB[ng] = (uint32_t)(wn + ng * 16 + ((lane >> 4) << 3) + x7) * 128u;
    for (int ch = 0; ch < CH_IN; ch++) {
        int st = ch & 1;
        mbar_wait(FULLB + st * 8, (uint32_t)((ch >> 1) & 1));
        uint32_t aB = STG + st * STGI, bB = aB + 8192;
#pragma unroll
        for (int ks = 0; ks < 4; ks++) {
            uint32_t cA = (uint32_t)(((ks * 2 + kuA) ^ x7) << 4);
            uint32_t cB = (uint32_t)(((ks * 2 + kuB) ^ x7) << 4);
            uint32_t Ah[2][4];
#pragma unroll
            for (int mt2 = 0; mt2 < 2; mt2++) ldsm4(Ah[mt2], aB + offA[mt2] + cA);
#pragma unroll
            for (int ng = 0; ng < 4; ng++) {
                uint32_t Bh[4];
                ldsm4(Bh, bB + offB[ng] + cB);
#pragma unroll
                for (int h = 0; h < 2; h++) {
                    int n8 = ng * 2 + h;
                    mma_f16(acc[0][n8], Ah[0], &Bh[h * 2]);
                    mma_f16(acc[1][n8], Ah[1], &Bh[h * 2]);
                }
            }
        }
        __syncthreads();
        if (tid == 0 && ch + 2 < CH_IN) issue(ch + 2, st);
    }
    float* tile = (float*)(basep + 1024);
#pragma unroll
    for (int mt2 = 0; mt2 < 2; mt2++)
#pragma unroll
        for (int half = 0; half < 2; half++) {
            int r = wm + mt2 * 16 + (lane >> 2) + half * 8;
            float* trow = tile + (size_t)r * 264;
#pragma unroll
            for (int n8 = 0; n8 < 8; n8++) {
                int col = wn + n8 * 8 + (lane & 3) * 2;
                float2 v = make_float2(acc[mt2][n8][half * 2 + 0] + bias[col],
                                       acc[mt2][n8][half * 2 + 1] + bias[col + 1]);
                *(float2*)&trow[col] = v;
            }
        }
    __syncthreads();
    float gv[8], bv[8];
#pragma unroll
    for (int j = 0; j < 8; j++) {
        int c = lane * 8 + j;
        gv[j] = __ldg(&gam[c]);
        bv[j] = __ldg(&bet[c]);
    }
    for (int rr = 0; rr < 8; rr++) {
        int row = wid * 8 + rr;
        const float* trow = tile + (size_t)row * 264 + lane * 8;
        float4 a = *(const float4*)trow;
        float4 b4 = *(const float4*)(trow + 4);
        float v[8] = {a.x, a.y, a.z, a.w, b4.x, b4.y, b4.z, b4.w};
        float s1 = 0.f, s2 = 0.f;
#pragma unroll
        for (int j = 0; j < 8; j++) { s1 += v[j]; s2 += v[j] * v[j]; }
#pragma unroll
        for (int o = 16; o > 0; o >>= 1) {
            s1 += __shfl_xor_sync(0xffffffffu, s1, o);
            s2 += __shfl_xor_sync(0xffffffffu, s2, o);
        }
        float mu = s1 * (1.f / 256.f);
        float rv = rsqrtf(s2 * (1.f / 256.f) - mu * mu + 1e-5f);
#pragma unroll
        for (int j = 0; j < 8; j++) v[j] = (v[j] - mu) * rv * gv[j] + bv[j];
        __align__(16) __half hv[8];
        cvt8(v, hv);
        int m = mtg * 64 + row;
        *(uint4*)&g_qh16[(size_t)m * 256 + lane * 8] = *(uint4*)hv;
        int b = m / HWN, p = m - b * HWN;
        {
            int og = lane >> 2, chin = (lane & 3) * 8;
            *(uint4*)&g_qog[(((size_t)(b * 8 + og)) * HWN + p) * 32 + chin] = *(uint4*)hv;
        }
        int y = p / 96, x = p - y * 96;
        size_t r_abs = (size_t)b * PROWS + 128 + (size_t)(y + 1) * PADW + (x + 1);
        int cq = lane >> 3, u = lane & 7;
        uint32_t sw = (uint32_t)(u * 16) ^ (((uint32_t)r_abs & 7) << 4);
        char* hb = (char*)(g_qpad + ((size_t)cq * QROWS + r_abs) * 64);
        *(uint4*)(hb + sw) = *(uint4*)hv;
    }
}

// ---- big conv GEMM (900 blocks) + sim0 tail (576 blocks) ----
#define STGB 40960
#define SMEM_BIG (1024 + 2 * STGB)
__global__ __launch_bounds__(256, 2) void gemm_big_k() {
    extern __shared__ char smraw[];
    char* basep = (char*)(((uintptr_t)smraw + 1023) & ~(uintptr_t)1023);
    uint32_t sb = smem_u32(basep);
    int bx = blockIdx.x;
    int tid = threadIdx.x;
    if (bx >= 900) {
        // sim0 branch
        float* psh = (float*)basep;
        int lane8 = tid & 7, pl = tid >> 3;
        int s = bx - 900;
        int b = s / 288;
        int pg = (s - b * 288) * 32 + pl;
        for (int i = tid; i < 768; i += 256) psh[i] = g_pool[b * 768 + i];
        __syncthreads();
        const __half* qrow = g_qh16 + ((size_t)b * HWN + pg) * 256;
        float acc6[6];
#pragma unroll
        for (int r = 0; r < 6; r++) acc6[r] = 0.f;
#pragma unroll
        for (int r = 0; r < 6; r++) {
            int g = (r >= 3) ? 1 : 0;
#pragma unroll
            for (int qq = 0; qq < 4; qq++) {
                int f = lane8 + qq * 8;
                uint2 t = *(const uint2*)&qrow[g * 128 + f * 4];
                float2 q0 = __half22float2(*(__half2*)&t.x);
                float2 q1 = __half22float2(*(__half2*)&t.y);
                float4 pv = *(const float4*)&psh[r * 128 + f * 4];
                acc6[r] += q0.x * pv.x + q0.y * pv.y + q1.x * pv.z + q1.y * pv.w;
            }
        }
#pragma unroll
        for (int r = 0; r < 6; r++) {
            acc6[r] += __shfl_xor_sync(0xffffffffu, acc6[r], 1);
            acc6[r] += __shfl_xor_sync(0xffffffffu, acc6[r], 2);
            acc6[r] += __shfl_xor_sync(0xffffffffu, acc6[r], 4);
        }
        if (lane8 == 0)
#pragma unroll
            for (int r = 0; r < 6; r++) g_sim[((size_t)b * 24 + r) * HWN + pg] = acc6[r];
        return;
    }
    int mtg = bx / 3, nt = bx - mtg * 3;
    int b = mtg / BT64, mt_local = mtg - b * BT64;
    size_t arowbase = (size_t)b * PROWS + 128 + (size_t)mt_local * 64;
    int wid = tid >> 5, lane = tid & 31;
    int wm = (wid & 1) * 32, wn = (wid >> 1) * 64;
    int ngm = 4;
    if (nt == 2) ngm = (wn == 128) ? 1 : (wn == 192) ? 0 : 4;
    uint32_t FULLB = sb, STG = sb + 1024;
    if (tid == 0)
        for (int s = 0; s < 2; s++) MBINIT(FULLB + s * 8, 1);
    __syncthreads();
    auto issue = [&](int ch, int st) {
        uint32_t S = STG + st * STGB;
        MBEXPECT(FULLB + st * 8, 40960u);
        int tap = ch >> 2, cq = ch & 3;
        int shift = (tap / 3 - 1) * PADW + (tap % 3 - 1);
        size_t row0 = arowbase + shift;
        bulk_g2s(S, g_qpad + ((size_t)cq * QROWS + row0) * 64, 8192u, FULLB + st * 8);
        bulk_g2s(S + 8192, g_Bbig + (size_t)(nt * CH_BIG + ch) * 16384, 32768u, FULLB + st * 8);
    };
    if (tid == 0) { issue(0, 0); issue(1, 1); }
    float acc[2][8][4];
#pragma unroll
    for (int a = 0; a < 2; a++)
#pragma unroll
        for (int n = 0; n < 8; n++)
#pragma unroll
            for (int c = 0; c < 4; c++) acc[a][n][c] = 0.f;
    int x7 = lane & 7, kuA = lane >> 4, kuB = (lane >> 3) & 1;
    uint32_t offA[2], offB[4];
#pragma unroll
    for (int mt2 = 0; mt2 < 2; mt2++)
        offA[mt2] = (uint32_t)(wm + mt2 * 16 + ((lane >> 3) & 1) * 8 + x7) * 128u;
#pragma unroll
    for (int ng = 0; ng < 4; ng++)
        offB[ng] = (uint32_t)(wn + ng * 16 + ((lane >> 4) << 3) + x7) * 128u;
    for (int ch = 0; ch < CH_BIG; ch++) {
        int st = ch & 1;
        mbar_wait(FULLB + st * 8, (uint32_t)((ch >> 1) & 1));
        uint32_t aB = STG + st * STGB, bB = aB + 8192;
        int tap = ch >> 2;
        int shift = (tap / 3 - 1) * PADW + (tap % 3 - 1);
        int xA = (x7 + shift) & 7;
        if (ngm == 4) {
#pragma unroll
            for (int ks = 0; ks < 4; ks++) {
                uint32_t cA = (uint32_t)(((ks * 2 + kuA) ^ xA) << 4);
                uint32_t cB = (uint32_t)(((ks * 2 + kuB) ^ x7) << 4);
                uint32_t Ah[2][4];
#pragma unroll
                for (int mt2 = 0; mt2 < 2; mt2++) ldsm4(Ah[mt2], aB + offA[mt2] + cA);
#pragma unroll
                for (int ng = 0; ng < 4; ng++) {
                    uint32_t Bh[4];
                    ldsm4(Bh, bB + offB[ng] + cB);
#pragma unroll
                    for (int h = 0; h < 2; h++) {
                        int n8 = ng * 2 + h;
                        mma_f16(acc[0][n8], Ah[0], &Bh[h * 2]);
                        mma_f16(acc[1][n8], Ah[1], &Bh[h * 2]);
                    }
                }
            }
        } else if (ngm == 1) {
#pragma unroll
            for (int ks = 0; ks < 4; ks++) {
                uint32_t cA = (uint32_t)(((ks * 2 + kuA) ^ xA) << 4);
                uint32_t cB = (uint32_t)(((ks * 2 + kuB) ^ x7) << 4);
                uint32_t Ah[2][4];
#pragma unroll
                for (int mt2 = 0; mt2 < 2; mt2++) ldsm4(Ah[mt2], aB + offA[mt2] + cA);
                uint32_t Bh[4];
                ldsm4(Bh, bB + offB[0] + cB);
#pragma unroll
                for (int h = 0; h < 2; h++) {
                    mma_f16(acc[0][h], Ah[0], &Bh[h * 2]);
                    mma_f16(acc[1][h], Ah[1], &Bh[h * 2]);
                }
            }
        }
        __syncthreads();
        if (tid == 0 && ch + 2 < CH_BIG) issue(ch + 2, st);
    }
#pragma unroll
    for (int mt2 = 0; mt2 < 2; mt2++)
#pragma unroll
        for (int half = 0; half < 2; half++) {
            int r = wm + mt2 * 16 + (lane >> 2) + half * 8;
            int pp = mt_local * 64 + r;
            int yq = pp / PADW, xq = pp - yq * PADW;
            bool ok = (yq >= 1) && (yq <= 96) && (xq >= 1) && (xq <= 96);
            if (!ok) continue;
            float* drow = g_conv2 + ((size_t)(b * HWN + (yq - 1) * 96 + xq - 1)) * RS_BIG;
#pragma unroll
            for (int n8 = 0; n8 < 8; n8++) {
                int col = nt * 256 + wn + n8 * 8 + (lane & 3) * 2;
                float2 v = make_float2(acc[mt2][n8][half * 2 + 0] + g_bpack[col],
                                       acc[mt2][n8][half * 2 + 1] + g_bpack[col + 1]);
                *(float2*)&drow[col] = v;
            }
        }
}

// ---- deform: fp16 weight staging, 41.5 KB smem, 1728 blocks ----
#define SMEM_DEF 41472
__global__ void deform_sim0() {
    extern __shared__ char shbuf[];
    int bx = blockIdx.x;
    int tid = threadIdx.x;
    int lane8 = tid & 7, pl = tid >> 3;
    __half* wshh = (__half*)shbuf;
    uint2* wtab = (uint2*)(shbuf + 13824);
    int* btab = (int*)(shbuf + 32256);
    int i0 = bx % 12;
    int rest = bx / 12;
    int j0 = rest % 24;
    int z = rest / 24;
    int b = z / 3, dz = z - b * 3;
    int dil = 1 << dz;
    int px = i0 * 8 + (pl & 7);
    int py = j0 * 4 + (pl >> 3);
    int p = py * 96 + px;
    for (int i = tid; i < 6912; i += 256) {
        int r = i / 1152;
        int rem = i - r * 1152;
        int tap = rem >> 7;
        int cg = rem & 127;
        int ex = r >> 1, half = r & 1;
        wshh[i] = __float2half_rn(
            g_sW[((size_t)(b * 3 + ex) * 256 + half * 128 + cg) * 9 + tap]);
    }
    const float* prow = g_conv2 + ((size_t)(b * HWN) + p) * RS_BIG + dz * 216;
    {
        const float* mrow = prow + 144;
        float vals[9];
        float mx = -1e30f;
#pragma unroll
        for (int t = 0; t < 9; t++) {
            vals[t] = __ldg(&mrow[lane8 * 9 + t]);
            mx = fmaxf(mx, vals[t]);
        }
        mx = fmaxf(mx, __shfl_xor_sync(0xffffffffu, mx, 1));
        mx = fmaxf(mx, __shfl_xor_sync(0xffffffffu, mx, 2));
        mx = fmaxf(mx, __shfl_xor_sync(0xffffffffu, mx, 4));
        float s = 0.f;
#pragma unroll
        for (int t = 0; t < 9; t++) { vals[t] = __expf(vals[t] - mx); s += vals[t]; }
        s += __shfl_xor_sync(0xffffffffu, s, 1);
        s += __shfl_xor_sync(0xffffffffu, s, 2);
        s += __shfl_xor_sync(0xffffffffu, s, 4);
        float inv = 1.f / s;
        int og = lane8;
        int ebase = (pl * 8 + og) * 9;
#pragma unroll
        for (int t = 0; t < 9; t++) {
            float m = vals[t] * inv;
            float dy = __ldg(&prow[og * 18 + t * 2]);
            float dx = __ldg(&prow[og * 18 + t * 2 + 1]);
            float fy = (float)(py + (t / 3) * dil - dil) + dy;
            float fx = (float)(px + (t % 3) * dil - dil) + dx;
            int y0 = (int)floorf(fy), x0 = (int)floorf(fx);
            int by = min(max(y0, 0), 94), bxm = min(max(x0, 0), 94);
            float wy0 = fmaxf(0.f, 1.f - fabsf(fy - (float)by));
            float wy1 = fmaxf(0.f, 1.f - fabsf(fy - (float)(by + 1)));
            float wx0 = fmaxf(0.f, 1.f - fabsf(fx - (float)bxm));
            float wx1 = fmaxf(0.f, 1.f - fabsf(fx - (float)(bxm + 1)));
            __half2 wA = __floats2half2_rn(wy0 * wx0 * m, wy0 * wx1 * m);
            __half2 wB = __floats2half2_rn(wy1 * wx0 * m, wy1 * wx1 * m);
            uint2 wp;
            wp.x = *(uint32_t*)&wA;
            wp.y = *(uint32_t*)&wB;
            wtab[ebase + t] = wp;
            btab[ebase + t] = (og * HWN + by * 96 + bxm) * 32;
        }
    }
    __syncthreads();
    const __half* qog = g_qog + (size_t)b * 8 * HWN * 32;
    int cb = lane8 * 4;
    float accr[6];
#pragma unroll
    for (int r = 0; r < 6; r++) accr[r] = 0.f;
#pragma unroll 2
    for (int og = 0; og < 8; og++) {
        int cgrp = (og & 3) * 32 + lane8 * 4;
        int rbase = (og < 4) ? 0 : 3;
        int ebase = (pl * 8 + og) * 9;
        float a0 = 0.f, a1 = 0.f, a2 = 0.f;
#pragma unroll
        for (int tap = 0; tap < 9; tap++) {
            uint2 wp = wtab[ebase + tap];
            int base = btab[ebase + tap];
            __half2 hA = *(__half2*)&wp.x;
            __half2 hB = *(__half2*)&wp.y;
            __half2 w00s = __low2half2(hA), w01s = __high2half2(hA);
            __half2 w10s = __low2half2(hB), w11s = __high2half2(hB);
            const __half* cb0 = qog + base + cb;
            uint2 t00 = *(const uint2*)(cb0);
            uint2 t01 = *(const uint2*)(cb0 + 32);
            uint2 t10 = *(const uint2*)(cb0 + 96 * 32);
            uint2 t11 = *(const uint2*)(cb0 + 97 * 32);
            __half2 s0 = __hmul2(w00s, *(__half2*)&t00.x);
            __half2 s1 = __hmul2(w00s, *(__half2*)&t00.y);
            s0 = __hfma2(w01s, *(__half2*)&t01.x, s0);
            s1 = __hfma2(w01s, *(__half2*)&t01.y, s1);
            s0 = __hfma2(w10s, *(__half2*)&t10.x, s0);
            s1 = __hfma2(w10s, *(__half2*)&t10.y, s1);
            s0 = __hfma2(w11s, *(__half2*)&t11.x, s0);
            s1 = __hfma2(w11s, *(__half2*)&t11.y, s1);
            float2 f0 = __half22float2(s0);
            float2 f1 = __half22float2(s1);
            uint2 wv0 = *(const uint2*)&wshh[((rbase + 0) * 9 + tap) * 128 + cgrp];
            float2 wa0 = __half22float2(*(__half2*)&wv0.x);
            float2 wb0 = __half22float2(*(__half2*)&wv0.y);
            a0 += f0.x * wa0.x + f0.y * wa0.y + f1.x * wb0.x + f1.y * wb0.y;
            uint2 wv1 = *(const uint2*)&wshh[((rbase + 1) * 9 + tap) * 128 + cgrp];
            float2 wa1 = __half22float2(*(__half2*)&wv1.x);
            float2 wb1 = __half22float2(*(__half2*)&wv1.y);
            a1 += f0.x * wa1.x + f0.y * wa1.y + f1.x * wb1.x + f1.y * wb1.y;
            uint2 wv2 = *(const uint2*)&wshh[((rbase + 2) * 9 + tap) * 128 + cgrp];
            float2 wa2 = __half22float2(*(__half2*)&wv2.x);
            float2 wb2 = __half22float2(*(__half2*)&wv2.y);
            a2 += f0.x * wa2.x + f0.y * wa2.y + f1.x * wb2.x + f1.y * wb2.y;
        }
        accr[rbase + 0] += a0;
        accr[rbase + 1] += a1;
        accr[rbase + 2] += a2;
    }
#pragma unroll
    for (int r = 0; r < 6; r++) {
        accr[r] += __shfl_xor_sync(0xffffffffu, accr[r], 1);
        accr[r] += __shfl_xor_sync(0xffffffffu, accr[r], 2);
        accr[r] += __shfl_xor_sync(0xffffffffu, accr[r], 4);
    }
    if (lane8 == 0) {
        size_t obase = ((size_t)b * 24 + 6 + dz * 6) * HWN + p;
#pragma unroll
        for (int r = 0; r < 6; r++) g_sim[obase + (size_t)r * HWN] = accr[r];
    }
}

__global__ void outconv_kernel(const float* __restrict__ ow, const float* __restrict__ ob,
                               float* __restrict__ out) {
    __shared__ float ws[256 * 25];
    __shared__ float st[24 * 65];
    int b = blockIdx.y;
    int m0 = blockIdx.x * 64;
    int tid = threadIdx.x;
    for (int i = tid; i < 6144; i += 256) {
        int oc = i / 24, k = i - oc * 24;
        ws[oc * 25 + k] = ow[i];
    }
    for (int i = tid; i < 24 * 64; i += 256) {
        int ch = i >> 6, j = i & 63;
        st[ch * 65 + j] = g_sim[((size_t)b * 24 + ch) * HWN + m0 + j];
    }
    __syncthreads();
    int j = tid & 63;
    int ocb = (tid >> 6) * 64;
    for (int oc = ocb; oc < ocb + 64; oc++) {
        float a = ob[oc];
#pragma unroll
        for (int k = 0; k < 24; k++) a += ws[oc * 25 + k] * st[k * 65 + j];
        out[((size_t)b * 256 + oc) * HWN + m0 + j] = a;
    }
}

extern "C" void kernel_launch(void* const* d_in, const int* in_sizes, int n_in,
                              void* d_out, int out_size) {
    const float* qf = (const float*)d_in[0];
    const float* sf = (const float*)d_in[1];
    const float* in_w = (const float*)d_in[2];
    const float* in_b = (const float*)d_in[3];
    const float* ln_g = (const float*)d_in[4];
    const float* ln_b = (const float*)d_in[5];
    const float* out_w = (const float*)d_in[6];
    const float* out_b = (const float*)d_in[7];
    const float* offw1 = (const float*)d_in[8];
    const float* offb1 = (const float*)d_in[9];
    const float* mskw1 = (const float*)d_in[10];
    const float* mskb1 = (const float*)d_in[11];
    const float* offw2 = (const float*)d_in[12];
    const float* offb2 = (const float*)d_in[13];
    const float* mskw2 = (const float*)d_in[14];
    const float* mskb2 = (const float*)d_in[15];
    const float* offw4 = (const float*)d_in[16];
    const float* offb4 = (const float*)d_in[17];
    const float* mskw4 = (const float*)d_in[18];
    const float* mskb4 = (const float*)d_in[19];
    float* out = (float*)d_out;

    cudaFuncSetAttribute(gemm_in_k, cudaFuncAttributeMaxDynamicSharedMemorySize, SMEM_IN);
    cudaFuncSetAttribute(gemm_big_k, cudaFuncAttributeMaxDynamicSharedMemorySize, SMEM_BIG);
    cudaFuncSetAttribute(deform_sim0, cudaFuncAttributeMaxDynamicSharedMemorySize, SMEM_DEF);

    prep_all<<<695, 256>>>(qf, sf, in_w, in_b, ln_g, ln_b,
                           offw1, mskw1, offw2, mskw2, offw4, mskw4,
                           offb1, mskb1, offb2, mskb2, offb4, mskb4);
    gemm_in_k<<<288, 256, SMEM_IN>>>(in_b, ln_g, ln_b);
    gemm_big_k<<<1476, 256, SMEM_BIG>>>();
    deform_sim0<<<1728, 256, SMEM_DEF>>>();
    outconv_kernel<<<dim3(144, 2), 256>>>(out_w, out_b, out);
}